// round 1
// baseline (speedup 1.0000x reference)
#include <cuda_runtime.h>

#define Bq   4
#define SEQ  2048
#define CH   768
#define NH   8
#define HDIM 96
#define MTOT (Bq*SEQ)     /* 8192 */
#define N1   (3*CH)       /* 2304 */

// ---------------- scratch (static __device__, no allocations) ----------------
__device__ float g_qkv[(size_t)MTOT * N1];          // 75.5 MB
__device__ float g_q[(size_t)Bq*NH*SEQ*HDIM];       // 25 MB, (b,h,s,d)
__device__ float g_k[(size_t)Bq*NH*SEQ*HDIM];
__device__ float g_v[(size_t)Bq*NH*SEQ*HDIM];
__device__ float g_ctx[(size_t)MTOT * CH];          // 25 MB, (b,s,C)

// ---------------- generic NT GEMM: C[m,n] = sum_k A[m,k]*B[n,k] (+bias) ------
// BM=BN=128, BK=16, 256 threads, 8x8 microtile. M,N multiples of 128, K of 16.
template<bool BIAS>
__global__ __launch_bounds__(256) void gemm_nt(const float* __restrict__ A,
                                               const float* __restrict__ Bw,
                                               const float* __restrict__ bias,
                                               float* __restrict__ Cmat,
                                               int Ntot, int Ktot)
{
    __shared__ float As[16][132];
    __shared__ float Bs[16][132];
    const int tid = threadIdx.x;
    const int tx  = tid & 15, ty = tid >> 4;
    const int m0  = blockIdx.y * 128, n0 = blockIdx.x * 128;

    float acc[8][8];
#pragma unroll
    for (int i = 0; i < 8; i++)
#pragma unroll
        for (int j = 0; j < 8; j++) acc[i][j] = 0.f;

    for (int k0 = 0; k0 < Ktot; k0 += 16) {
#pragma unroll
        for (int i = 0; i < 2; i++) {
            int idx = tid + i * 256;
            int r   = idx >> 2;
            int c4  = (idx & 3) << 2;
            float4 va = *(const float4*)(A  + (size_t)(m0 + r) * Ktot + k0 + c4);
            As[c4+0][r] = va.x; As[c4+1][r] = va.y; As[c4+2][r] = va.z; As[c4+3][r] = va.w;
            float4 vb = *(const float4*)(Bw + (size_t)(n0 + r) * Ktot + k0 + c4);
            Bs[c4+0][r] = vb.x; Bs[c4+1][r] = vb.y; Bs[c4+2][r] = vb.z; Bs[c4+3][r] = vb.w;
        }
        __syncthreads();
#pragma unroll
        for (int kk = 0; kk < 16; kk++) {
            float a[8], b[8];
            *(float4*)&a[0] = *(const float4*)&As[kk][ty*8];
            *(float4*)&a[4] = *(const float4*)&As[kk][ty*8+4];
            *(float4*)&b[0] = *(const float4*)&Bs[kk][tx*8];
            *(float4*)&b[4] = *(const float4*)&Bs[kk][tx*8+4];
#pragma unroll
            for (int i = 0; i < 8; i++)
#pragma unroll
                for (int j = 0; j < 8; j++)
                    acc[i][j] = fmaf(a[i], b[j], acc[i][j]);
        }
        __syncthreads();
    }

#pragma unroll
    for (int i = 0; i < 8; i++) {
        int m = m0 + ty*8 + i;
#pragma unroll
        for (int j = 0; j < 8; j += 4) {
            int n = n0 + tx*8 + j;
            float4 v;
            v.x = acc[i][j+0]; v.y = acc[i][j+1]; v.z = acc[i][j+2]; v.w = acc[i][j+3];
            if (BIAS) { v.x += bias[n]; v.y += bias[n+1]; v.z += bias[n+2]; v.w += bias[n+3]; }
            *(float4*)(Cmat + (size_t)m * Ntot + n) = v;
        }
    }
}

// ---------------- RoPE (interleaved) + scatter to (b,h,s,d) ------------------
__global__ void rope_scatter(const float* __restrict__ qkv,
                             const float* __restrict__ cosb,
                             const float* __restrict__ sinb)
{
    int idx = blockIdx.x * blockDim.x + threadIdx.x;   // one thread per (even,odd) pair
    const int PAIRS = MTOT * (N1 / 2);
    if (idx >= PAIRS) return;
    int m     = idx / (N1 / 2);
    int pc    = (idx - m * (N1 / 2)) * 2;              // even column in [0,2304)
    int which = pc / CH;                               // 0:q 1:k 2:v
    int c     = pc - which * CH;
    int h     = c / HDIM;
    int d     = c - h * HDIM;                          // even
    int b     = m >> 11, s = m & (SEQ - 1);

    float2 x = *(const float2*)(qkv + (size_t)m * N1 + pc);
    size_t o = ((size_t)(b * NH + h) * SEQ + s) * HDIM + d;
    if (which == 2) {
        *(float2*)(g_v + o) = x;
    } else {
        float cs = cosb[s * HDIM + d];
        float sn = sinb[s * HDIM + d];
        float2 y;
        y.x = x.x * cs - x.y * sn;   // t*cos + rotate_half(t)*sin, rh[2i]  = -t[2i+1]
        y.y = x.y * cs + x.x * sn;   //                              rh[2i+1]=  t[2i]
        float* dst = (which == 0) ? g_q : g_k;
        *(float2*)(dst + o) = y;
    }
}

// ---------------- flash attention: BM=BN=128, HD=96, fp32 --------------------
// smem: sQ[96][132] (k-major transposed), sK[96][132], sV[128][100], sS[128][132]
__global__ __launch_bounds__(256, 1) void flash_attn(float* __restrict__ ctx)
{
    extern __shared__ float sm[];
    float* sQ = sm;                  // 96*132  = 12672
    float* sK = sQ + 96 * 132;       // 12672
    float* sV = sK + 96 * 132;       // 128*100 = 12800
    float* sS = sV + 128 * 100;      // 128*132 = 16896
    float* sM = sS + 128 * 132;      // 128
    float* sL = sM + 128;            // 128
    float* sC = sL + 128;            // 128

    const int tid = threadIdx.x;
    const int tx  = tid & 15, ty = tid >> 4;
    const int bh  = blockIdx.y;                 // b*NH + h
    const int q0  = blockIdx.x * 128;
    const float scale = 0.10206207261596575f;   // 96^-0.5
    const float NEG_INF = __int_as_float(0xff800000);

    // ---- load Q tile transposed: sQ[d][m] ----
    const float* Qg = g_q + ((size_t)bh * SEQ + q0) * HDIM;
#pragma unroll
    for (int i = 0; i < 12; i++) {
        int idx = tid + i * 256;                // 0..3071
        int r   = idx / 24;
        int c4  = (idx - r * 24) * 4;
        float4 v = *(const float4*)(Qg + r * HDIM + c4);
        sQ[(c4+0)*132 + r] = v.x;
        sQ[(c4+1)*132 + r] = v.y;
        sQ[(c4+2)*132 + r] = v.z;
        sQ[(c4+3)*132 + r] = v.w;
    }
    if (tid < 128) { sM[tid] = NEG_INF; sL[tid] = 0.f; }

    float o[8][6];
#pragma unroll
    for (int i = 0; i < 8; i++)
#pragma unroll
        for (int j = 0; j < 6; j++) o[i][j] = 0.f;

    for (int t = 0; t < SEQ / 128; t++) {
        const float* Kg = g_k + ((size_t)bh * SEQ + t * 128) * HDIM;
        const float* Vg = g_v + ((size_t)bh * SEQ + t * 128) * HDIM;
#pragma unroll
        for (int i = 0; i < 12; i++) {
            int idx = tid + i * 256;
            int r   = idx / 24;
            int c4  = (idx - r * 24) * 4;
            float4 vk = *(const float4*)(Kg + r * HDIM + c4);
            sK[(c4+0)*132 + r] = vk.x;
            sK[(c4+1)*132 + r] = vk.y;
            sK[(c4+2)*132 + r] = vk.z;
            sK[(c4+3)*132 + r] = vk.w;
            float4 vv = *(const float4*)(Vg + r * HDIM + c4);
            *(float4*)(sV + r * 100 + c4) = vv;
        }
        __syncthreads();

        // ---- S = Q K^T (128x128, k=96) ----
        float s_[8][8];
#pragma unroll
        for (int i = 0; i < 8; i++)
#pragma unroll
            for (int j = 0; j < 8; j++) s_[i][j] = 0.f;

#pragma unroll 4
        for (int d = 0; d < HDIM; d++) {
            float a[8], b[8];
            *(float4*)&a[0] = *(const float4*)&sQ[d*132 + ty*8];
            *(float4*)&a[4] = *(const float4*)&sQ[d*132 + ty*8 + 4];
            *(float4*)&b[0] = *(const float4*)&sK[d*132 + tx*8];
            *(float4*)&b[4] = *(const float4*)&sK[d*132 + tx*8 + 4];
#pragma unroll
            for (int i = 0; i < 8; i++)
#pragma unroll
                for (int j = 0; j < 8; j++)
                    s_[i][j] = fmaf(a[i], b[j], s_[i][j]);
        }
#pragma unroll
        for (int i = 0; i < 8; i++) {
            float4 w0, w1;
            w0.x = s_[i][0]*scale; w0.y = s_[i][1]*scale; w0.z = s_[i][2]*scale; w0.w = s_[i][3]*scale;
            w1.x = s_[i][4]*scale; w1.y = s_[i][5]*scale; w1.z = s_[i][6]*scale; w1.w = s_[i][7]*scale;
            *(float4*)&sS[(ty*8+i)*132 + tx*8]     = w0;
            *(float4*)&sS[(ty*8+i)*132 + tx*8 + 4] = w1;
        }
        __syncthreads();

        // ---- online softmax (one thread per row) ----
        if (tid < 128) {
            float* row = sS + tid * 132;
            float tm = NEG_INF;
#pragma unroll 8
            for (int n = 0; n < 128; n++) tm = fmaxf(tm, row[n]);
            float mold = sM[tid];
            float mnew = fmaxf(mold, tm);
            float corr = __expf(mold - mnew);
            float lsum = 0.f;
#pragma unroll 4
            for (int n = 0; n < 128; n++) {
                float p = __expf(row[n] - mnew);
                row[n]  = p;
                lsum   += p;
            }
            sL[tid] = sL[tid] * corr + lsum;
            sM[tid] = mnew;
            sC[tid] = corr;
        }
        __syncthreads();

        // ---- rescale O, then O += P V ----
        float corr[8];
#pragma unroll
        for (int i = 0; i < 8; i++) corr[i] = sC[ty*8 + i];
#pragma unroll
        for (int i = 0; i < 8; i++)
#pragma unroll
            for (int j = 0; j < 6; j++) o[i][j] *= corr[i];

#pragma unroll 2
        for (int kk = 0; kk < 128; kk++) {
            float p[8];
#pragma unroll
            for (int i = 0; i < 8; i++) p[i] = sS[(ty*8+i)*132 + kk];
            float2 v0 = *(const float2*)&sV[kk*100 + tx*6];
            float2 v1 = *(const float2*)&sV[kk*100 + tx*6 + 2];
            float2 v2 = *(const float2*)&sV[kk*100 + tx*6 + 4];
#pragma unroll
            for (int i = 0; i < 8; i++) {
                o[i][0] = fmaf(p[i], v0.x, o[i][0]);
                o[i][1] = fmaf(p[i], v0.y, o[i][1]);
                o[i][2] = fmaf(p[i], v1.x, o[i][2]);
                o[i][3] = fmaf(p[i], v1.y, o[i][3]);
                o[i][4] = fmaf(p[i], v2.x, o[i][4]);
                o[i][5] = fmaf(p[i], v2.y, o[i][5]);
            }
        }
        __syncthreads();
    }

    // ---- epilogue: ctx[b, s, h*96 + c] = o / l ----
    const int h = bh & (NH - 1), b = bh >> 3;
#pragma unroll
    for (int i = 0; i < 8; i++) {
        int r = q0 + ty*8 + i;
        float linv = 1.f / sL[ty*8 + i];
        float* dst = ctx + ((size_t)b * SEQ + r) * CH + h * HDIM + tx * 6;
        float2 w;
        w.x = o[i][0]*linv; w.y = o[i][1]*linv; *(float2*)(dst)     = w;
        w.x = o[i][2]*linv; w.y = o[i][3]*linv; *(float2*)(dst + 2) = w;
        w.x = o[i][4]*linv; w.y = o[i][5]*linv; *(float2*)(dst + 4) = w;
    }
}

// ------------------------------ launch ---------------------------------------
extern "C" void kernel_launch(void* const* d_in, const int* in_sizes, int n_in,
                              void* d_out, int out_size)
{
    const float* x     = (const float*)d_in[0];
    const float* cosb  = (const float*)d_in[1];
    const float* sinb  = (const float*)d_in[2];
    const float* Wqkv  = (const float*)d_in[3];
    const float* Wproj = (const float*)d_in[4];
    const float* bproj = (const float*)d_in[5];
    float* out = (float*)d_out;

    float *qkv, *ctx;
    cudaGetSymbolAddress((void**)&qkv, g_qkv);
    cudaGetSymbolAddress((void**)&ctx, g_ctx);

    const size_t shm = (size_t)(2*96*132 + 128*100 + 128*132 + 3*128) * sizeof(float); // 221,696 B
    cudaFuncSetAttribute(flash_attn, cudaFuncAttributeMaxDynamicSharedMemorySize, (int)shm);

    // 1) qkv = x @ Wqkv^T            (8192 x 2304, K=768)
    dim3 g1(N1 / 128, MTOT / 128);
    gemm_nt<false><<<g1, 256>>>(x, Wqkv, nullptr, qkv, N1, CH);

    // 2) RoPE + scatter to (b,h,s,d)
    int pairs = MTOT * (N1 / 2);
    rope_scatter<<<(pairs + 255) / 256, 256>>>(qkv, cosb, sinb);

    // 3) flash attention -> ctx (b,s,C)
    dim3 g2(SEQ / 128, Bq * NH);
    flash_attn<<<g2, 256, shm>>>(ctx);

    // 4) out = ctx @ Wproj^T + bproj (8192 x 768, K=768)
    dim3 g3(CH / 128, MTOT / 128);
    gemm_nt<true><<<g3, 256>>>(ctx, Wproj, bproj, out, CH, CH);
}

// round 2
// speedup vs baseline: 1.0473x; 1.0473x over previous
#include <cuda_runtime.h>

#define Bq   4
#define SEQ  2048
#define CH   768
#define NH   8
#define HDIM 96
#define MTOT (Bq*SEQ)     /* 8192 */
#define N1   (3*CH)       /* 2304 */

typedef unsigned long long u64;

// ---- packed f32x2 helpers (sm_103a) -----------------------------------------
__device__ __forceinline__ u64 pack2(float x) {
    u64 r;
    asm("mov.b64 %0, {%1, %1};" : "=l"(r) : "r"(__float_as_uint(x)));
    return r;
}
__device__ __forceinline__ void ffma2(u64& d, u64 a, u64 b) {
    asm("fma.rn.f32x2 %0, %1, %2, %0;" : "+l"(d) : "l"(a), "l"(b));
}
__device__ __forceinline__ void mul2(u64& d, u64 a) {
    asm("mul.rn.f32x2 %0, %0, %1;" : "+l"(d) : "l"(a));
}
__device__ __forceinline__ float2 unpack2(u64 v) {
    unsigned lo, hi;
    asm("mov.b64 {%0, %1}, %2;" : "=r"(lo), "=r"(hi) : "l"(v));
    return make_float2(__uint_as_float(lo), __uint_as_float(hi));
}

// ---------------- scratch (static __device__, no allocations) ----------------
__device__ float g_qkv[(size_t)MTOT * N1];          // 75.5 MB
__device__ float g_q[(size_t)Bq*NH*SEQ*HDIM];       // 25 MB, (b,h,s,d)
__device__ float g_k[(size_t)Bq*NH*SEQ*HDIM];
__device__ float g_v[(size_t)Bq*NH*SEQ*HDIM];
__device__ float g_ctx[(size_t)MTOT * CH];          // 25 MB, (b,s,C)

// ---------------- generic NT GEMM: C[m,n] = sum_k A[m,k]*B[n,k] (+bias) ------
// BM=BN=128, BK=16, 256 threads, 8x8 microtile as 8x4 f32x2 pairs.
template<bool BIAS>
__global__ __launch_bounds__(256) void gemm_nt(const float* __restrict__ A,
                                               const float* __restrict__ Bw,
                                               const float* __restrict__ bias,
                                               float* __restrict__ Cmat,
                                               int Ntot, int Ktot)
{
    __shared__ float As[16][132];
    __shared__ float Bs[16][132];
    const int tid = threadIdx.x;
    const int tx  = tid & 15, ty = tid >> 4;
    const int m0  = blockIdx.y * 128, n0 = blockIdx.x * 128;

    u64 acc[8][4];
#pragma unroll
    for (int i = 0; i < 8; i++)
#pragma unroll
        for (int j = 0; j < 4; j++) acc[i][j] = 0ull;

    for (int k0 = 0; k0 < Ktot; k0 += 16) {
#pragma unroll
        for (int i = 0; i < 2; i++) {
            int idx = tid + i * 256;
            int r   = idx >> 2;
            int c4  = (idx & 3) << 2;
            float4 va = *(const float4*)(A  + (size_t)(m0 + r) * Ktot + k0 + c4);
            As[c4+0][r] = va.x; As[c4+1][r] = va.y; As[c4+2][r] = va.z; As[c4+3][r] = va.w;
            float4 vb = *(const float4*)(Bw + (size_t)(n0 + r) * Ktot + k0 + c4);
            Bs[c4+0][r] = vb.x; Bs[c4+1][r] = vb.y; Bs[c4+2][r] = vb.z; Bs[c4+3][r] = vb.w;
        }
        __syncthreads();
#pragma unroll
        for (int kk = 0; kk < 16; kk++) {
            float a[8];
            *(float4*)&a[0] = *(const float4*)&As[kk][ty*8];
            *(float4*)&a[4] = *(const float4*)&As[kk][ty*8+4];
            ulonglong2 b01 = *(const ulonglong2*)&Bs[kk][tx*8];
            ulonglong2 b23 = *(const ulonglong2*)&Bs[kk][tx*8+4];
            u64 b2[4]; b2[0] = b01.x; b2[1] = b01.y; b2[2] = b23.x; b2[3] = b23.y;
#pragma unroll
            for (int i = 0; i < 8; i++) {
                u64 a2 = pack2(a[i]);
#pragma unroll
                for (int j = 0; j < 4; j++) ffma2(acc[i][j], a2, b2[j]);
            }
        }
        __syncthreads();
    }

#pragma unroll
    for (int i = 0; i < 8; i++) {
        int m = m0 + ty*8 + i;
        float2 p0 = unpack2(acc[i][0]), p1 = unpack2(acc[i][1]);
        float2 p2 = unpack2(acc[i][2]), p3 = unpack2(acc[i][3]);
        int n = n0 + tx*8;
        float4 v0 = make_float4(p0.x, p0.y, p1.x, p1.y);
        float4 v1 = make_float4(p2.x, p2.y, p3.x, p3.y);
        if (BIAS) {
            v0.x += bias[n+0]; v0.y += bias[n+1]; v0.z += bias[n+2]; v0.w += bias[n+3];
            v1.x += bias[n+4]; v1.y += bias[n+5]; v1.z += bias[n+6]; v1.w += bias[n+7];
        }
        *(float4*)(Cmat + (size_t)m * Ntot + n)     = v0;
        *(float4*)(Cmat + (size_t)m * Ntot + n + 4) = v1;
    }
}

// ---------------- RoPE (interleaved) + scatter to (b,h,s,d) ------------------
// Q additionally pre-scaled by HD^-0.5 so flash skips the scale.
__global__ void rope_scatter(const float* __restrict__ qkv,
                             const float* __restrict__ cosb,
                             const float* __restrict__ sinb)
{
    int idx = blockIdx.x * blockDim.x + threadIdx.x;   // one thread per (even,odd) pair
    const int PAIRS = MTOT * (N1 / 2);
    if (idx >= PAIRS) return;
    int m     = idx / (N1 / 2);
    int pc    = (idx - m * (N1 / 2)) * 2;              // even column in [0,2304)
    int which = pc / CH;                               // 0:q 1:k 2:v
    int c     = pc - which * CH;
    int h     = c / HDIM;
    int d     = c - h * HDIM;                          // even
    int b     = m >> 11, s = m & (SEQ - 1);
    const float scale = 0.10206207261596575f;          // 96^-0.5

    float2 x = *(const float2*)(qkv + (size_t)m * N1 + pc);
    size_t o = ((size_t)(b * NH + h) * SEQ + s) * HDIM + d;
    if (which == 2) {
        *(float2*)(g_v + o) = x;
    } else {
        float cs = cosb[s * HDIM + d];
        float sn = sinb[s * HDIM + d];
        float2 y;
        y.x = x.x * cs - x.y * sn;
        y.y = x.y * cs + x.x * sn;
        if (which == 0) { y.x *= scale; y.y *= scale; *(float2*)(g_q + o) = y; }
        else            { *(float2*)(g_k + o) = y; }
    }
}

// ---------------- flash attention: BM=BN=128, HD=96, fp32, f32x2 -------------
// smem: sQ[96][132] (d-major), sK[96][132], sV[128][100], sS[128][132]
__global__ __launch_bounds__(256, 1) void flash_attn(float* __restrict__ ctx)
{
    extern __shared__ float sm[];
    float* sQ = sm;                  // 96*132  = 12672
    float* sK = sQ + 96 * 132;       // 12672
    float* sV = sK + 96 * 132;       // 128*100 = 12800
    float* sS = sV + 128 * 100;      // 128*132 = 16896

    const int tid = threadIdx.x;
    const int tx  = tid & 15, ty = tid >> 4;
    const int bh  = blockIdx.y;
    const int q0  = blockIdx.x * 128;
    const float NEG_INF = __int_as_float(0xff800000);

    // ---- load Q tile transposed: sQ[d][m] ----
    const float* Qg = g_q + ((size_t)bh * SEQ + q0) * HDIM;
#pragma unroll
    for (int i = 0; i < 12; i++) {
        int idx = tid + i * 256;
        int r   = idx / 24;
        int c4  = (idx - r * 24) * 4;
        float4 v = *(const float4*)(Qg + r * HDIM + c4);
        sQ[(c4+0)*132 + r] = v.x;
        sQ[(c4+1)*132 + r] = v.y;
        sQ[(c4+2)*132 + r] = v.z;
        sQ[(c4+3)*132 + r] = v.w;
    }

    // per-thread softmax state for its 8 rows (replicated across the row's 16 lanes)
    float mrow[8], lrow[8];
#pragma unroll
    for (int i = 0; i < 8; i++) { mrow[i] = NEG_INF; lrow[i] = 0.f; }

    u64 o2[8][3];
#pragma unroll
    for (int i = 0; i < 8; i++)
#pragma unroll
        for (int j = 0; j < 3; j++) o2[i][j] = 0ull;

    for (int t = 0; t < SEQ / 128; t++) {
        __syncthreads();   // prev PV done reading sS/sV; Q visible on t=0
        const float* Kg = g_k + ((size_t)bh * SEQ + t * 128) * HDIM;
        const float* Vg = g_v + ((size_t)bh * SEQ + t * 128) * HDIM;
#pragma unroll
        for (int i = 0; i < 12; i++) {
            int idx = tid + i * 256;
            int r   = idx / 24;
            int c4  = (idx - r * 24) * 4;
            float4 vk = *(const float4*)(Kg + r * HDIM + c4);
            sK[(c4+0)*132 + r] = vk.x;
            sK[(c4+1)*132 + r] = vk.y;
            sK[(c4+2)*132 + r] = vk.z;
            sK[(c4+3)*132 + r] = vk.w;
            float4 vv = *(const float4*)(Vg + r * HDIM + c4);
            *(float4*)(sV + r * 100 + c4) = vv;
        }
        __syncthreads();

        // ---- S = Q K^T (128x128, k=96), pairs along j ----
        u64 s2[8][4];
#pragma unroll
        for (int i = 0; i < 8; i++)
#pragma unroll
            for (int j = 0; j < 4; j++) s2[i][j] = 0ull;

#pragma unroll 4
        for (int d = 0; d < HDIM; d++) {
            float a[8];
            *(float4*)&a[0] = *(const float4*)&sQ[d*132 + ty*8];
            *(float4*)&a[4] = *(const float4*)&sQ[d*132 + ty*8 + 4];
            ulonglong2 b01 = *(const ulonglong2*)&sK[d*132 + tx*8];
            ulonglong2 b23 = *(const ulonglong2*)&sK[d*132 + tx*8 + 4];
            u64 b2[4]; b2[0] = b01.x; b2[1] = b01.y; b2[2] = b23.x; b2[3] = b23.y;
#pragma unroll
            for (int i = 0; i < 8; i++) {
                u64 a2 = pack2(a[i]);
#pragma unroll
                for (int j = 0; j < 4; j++) ffma2(s2[i][j], a2, b2[j]);
            }
        }

        // ---- online softmax fully in registers ----
        float s[8][8];
#pragma unroll
        for (int i = 0; i < 8; i++) {
#pragma unroll
            for (int j = 0; j < 4; j++) {
                float2 p = unpack2(s2[i][j]);
                s[i][2*j] = p.x; s[i][2*j+1] = p.y;
            }
        }
        float corr[8];
#pragma unroll
        for (int i = 0; i < 8; i++) {
            float rm = s[i][0];
#pragma unroll
            for (int j = 1; j < 8; j++) rm = fmaxf(rm, s[i][j]);
            rm = fmaxf(rm, __shfl_xor_sync(0xffffffffu, rm, 1));
            rm = fmaxf(rm, __shfl_xor_sync(0xffffffffu, rm, 2));
            rm = fmaxf(rm, __shfl_xor_sync(0xffffffffu, rm, 4));
            rm = fmaxf(rm, __shfl_xor_sync(0xffffffffu, rm, 8));
            float mnew = fmaxf(mrow[i], rm);
            float c = __expf(mrow[i] - mnew);
            mrow[i] = mnew;
            corr[i] = c;
            float sum = 0.f;
#pragma unroll
            for (int j = 0; j < 8; j++) {
                float p = __expf(s[i][j] - mnew);
                s[i][j] = p;
                sum += p;
            }
            sum += __shfl_xor_sync(0xffffffffu, sum, 1);
            sum += __shfl_xor_sync(0xffffffffu, sum, 2);
            sum += __shfl_xor_sync(0xffffffffu, sum, 4);
            sum += __shfl_xor_sync(0xffffffffu, sum, 8);
            lrow[i] = lrow[i] * c + sum;
        }

        // ---- store P row-major ----
#pragma unroll
        for (int i = 0; i < 8; i++) {
            float4 w0 = make_float4(s[i][0], s[i][1], s[i][2], s[i][3]);
            float4 w1 = make_float4(s[i][4], s[i][5], s[i][6], s[i][7]);
            *(float4*)&sS[(ty*8+i)*132 + tx*8]     = w0;
            *(float4*)&sS[(ty*8+i)*132 + tx*8 + 4] = w1;
        }
        __syncthreads();

        // ---- rescale O, then O += P V (pairs along d) ----
#pragma unroll
        for (int i = 0; i < 8; i++) {
            u64 c2 = pack2(corr[i]);
#pragma unroll
            for (int j = 0; j < 3; j++) mul2(o2[i][j], c2);
        }

#pragma unroll 2
        for (int kk = 0; kk < 128; kk++) {
            float p[8];
#pragma unroll
            for (int i = 0; i < 8; i++) p[i] = sS[(ty*8+i)*132 + kk];   // broadcast
            u64 v0 = *(const u64*)&sV[kk*100 + tx*6];
            u64 v1 = *(const u64*)&sV[kk*100 + tx*6 + 2];
            u64 v2 = *(const u64*)&sV[kk*100 + tx*6 + 4];
#pragma unroll
            for (int i = 0; i < 8; i++) {
                u64 a2 = pack2(p[i]);
                ffma2(o2[i][0], a2, v0);
                ffma2(o2[i][1], a2, v1);
                ffma2(o2[i][2], a2, v2);
            }
        }
    }

    // ---- epilogue: ctx[b, s, h*96 + c] = o / l ----
    const int h = bh & (NH - 1), b = bh >> 3;
#pragma unroll
    for (int i = 0; i < 8; i++) {
        int r = q0 + ty*8 + i;
        float linv = 1.f / lrow[i];
        float* dst = ctx + ((size_t)b * SEQ + r) * CH + h * HDIM + tx * 6;
        float2 a0 = unpack2(o2[i][0]);
        float2 a1 = unpack2(o2[i][1]);
        float2 a2 = unpack2(o2[i][2]);
        a0.x *= linv; a0.y *= linv; *(float2*)(dst)     = a0;
        a1.x *= linv; a1.y *= linv; *(float2*)(dst + 2) = a1;
        a2.x *= linv; a2.y *= linv; *(float2*)(dst + 4) = a2;
    }
}

// ------------------------------ launch ---------------------------------------
extern "C" void kernel_launch(void* const* d_in, const int* in_sizes, int n_in,
                              void* d_out, int out_size)
{
    const float* x     = (const float*)d_in[0];
    const float* cosb  = (const float*)d_in[1];
    const float* sinb  = (const float*)d_in[2];
    const float* Wqkv  = (const float*)d_in[3];
    const float* Wproj = (const float*)d_in[4];
    const float* bproj = (const float*)d_in[5];
    float* out = (float*)d_out;

    float *qkv, *ctx;
    cudaGetSymbolAddress((void**)&qkv, g_qkv);
    cudaGetSymbolAddress((void**)&ctx, g_ctx);

    const size_t shm = (size_t)(2*96*132 + 128*100 + 128*132) * sizeof(float); // 220,160 B
    cudaFuncSetAttribute(flash_attn, cudaFuncAttributeMaxDynamicSharedMemorySize, (int)shm);

    // 1) qkv = x @ Wqkv^T            (8192 x 2304, K=768)
    dim3 g1(N1 / 128, MTOT / 128);
    gemm_nt<false><<<g1, 256>>>(x, Wqkv, nullptr, qkv, N1, CH);

    // 2) RoPE + scatter to (b,h,s,d); q pre-scaled
    int pairs = MTOT * (N1 / 2);
    rope_scatter<<<(pairs + 255) / 256, 256>>>(qkv, cosb, sinb);

    // 3) flash attention -> ctx (b,s,C)
    dim3 g2(SEQ / 128, Bq * NH);
    flash_attn<<<g2, 256, shm>>>(ctx);

    // 4) out = ctx @ Wproj^T + bproj (8192 x 768, K=768)
    dim3 g3(CH / 128, MTOT / 128);
    gemm_nt<true><<<g3, 256>>>(ctx, Wproj, bproj, out, CH, CH);
}

// round 4
// speedup vs baseline: 1.3026x; 1.2438x over previous
#include <cuda_runtime.h>
#include <cuda_bf16.h>
#include <cstdint>

#define Bq   4
#define SEQ  2048
#define CH   768
#define NH   8
#define HDIM 96
#define MTOT (Bq*SEQ)     /* 8192 */
#define N1   (3*CH)       /* 2304 */

typedef unsigned long long u64;

// ---- packed f32x2 helpers (sm_103a) -----------------------------------------
__device__ __forceinline__ u64 pack2(float x) {
    u64 r;
    asm("mov.b64 %0, {%1, %1};" : "=l"(r) : "r"(__float_as_uint(x)));
    return r;
}
__device__ __forceinline__ void ffma2(u64& d, u64 a, u64 b) {
    asm("fma.rn.f32x2 %0, %1, %2, %0;" : "+l"(d) : "l"(a), "l"(b));
}
__device__ __forceinline__ void mul2(u64& d, u64 a) {
    asm("mul.rn.f32x2 %0, %0, %1;" : "+l"(d) : "l"(a));
}
__device__ __forceinline__ float2 unpack2(u64 v) {
    unsigned lo, hi;
    asm("mov.b64 {%0, %1}, %2;" : "=r"(lo), "=r"(hi) : "l"(v));
    return make_float2(__uint_as_float(lo), __uint_as_float(hi));
}

// ---- HMMA helpers (baseline PTX, sm_80+) -------------------------------------
__device__ __forceinline__ uint32_t smem_u32(const void* p) {
    uint32_t a;
    asm("{ .reg .u64 t; cvta.to.shared.u64 t, %1; cvt.u32.u64 %0, t; }" : "=r"(a) : "l"(p));
    return a;
}
__device__ __forceinline__ void ldsm4(uint32_t* r, uint32_t addr) {
    asm volatile("ldmatrix.sync.aligned.m8n8.x4.shared.b16 {%0,%1,%2,%3}, [%4];"
        : "=r"(r[0]), "=r"(r[1]), "=r"(r[2]), "=r"(r[3]) : "r"(addr));
}
__device__ __forceinline__ void mma_bf16(float* d, const uint32_t* a, const uint32_t* b) {
    asm volatile("mma.sync.aligned.m16n8k16.row.col.f32.bf16.bf16.f32 "
        "{%0,%1,%2,%3}, {%4,%5,%6,%7}, {%8,%9}, {%0,%1,%2,%3};"
        : "+f"(d[0]), "+f"(d[1]), "+f"(d[2]), "+f"(d[3])
        : "r"(a[0]), "r"(a[1]), "r"(a[2]), "r"(a[3]), "r"(b[0]), "r"(b[1]));
}

// ---------------- scratch (static __device__, no allocations) ----------------
__device__ float g_qkv[(size_t)MTOT * N1];          // 75.5 MB
__device__ float g_q[(size_t)Bq*NH*SEQ*HDIM];       // 25 MB, (b,h,s,d)
__device__ float g_k[(size_t)Bq*NH*SEQ*HDIM];
__device__ float g_v[(size_t)Bq*NH*SEQ*HDIM];
__device__ float g_ctx[(size_t)MTOT * CH];          // 25 MB, (b,s,C)

// ---- fp32 -> (hi,lo) bf16 split, 4 elems, 8B each ----------------------------
__device__ __forceinline__ void store_split(char* smem, uint32_t offH, uint32_t offL, float4 v) {
    uint32_t b0 = __float_as_uint(v.x), b1 = __float_as_uint(v.y);
    uint32_t b2 = __float_as_uint(v.z), b3 = __float_as_uint(v.w);
    uint2 hi;
    hi.x = __byte_perm(b0, b1, 0x7632);   // {bf16 trunc(x), bf16 trunc(y)}
    hi.y = __byte_perm(b2, b3, 0x7632);
    float l0 = v.x - __uint_as_float(b0 & 0xffff0000u);   // exact residual
    float l1 = v.y - __uint_as_float(b1 & 0xffff0000u);
    float l2 = v.z - __uint_as_float(b2 & 0xffff0000u);
    float l3 = v.w - __uint_as_float(b3 & 0xffff0000u);
    uint2 lo;
    asm("cvt.rn.bf16x2.f32 %0, %1, %2;" : "=r"(lo.x) : "f"(l1), "f"(l0));
    asm("cvt.rn.bf16x2.f32 %0, %1, %2;" : "=r"(lo.y) : "f"(l3), "f"(l2));
    *(uint2*)(smem + offH) = hi;
    *(uint2*)(smem + offL) = lo;
}

// ---------------- HMMA NT GEMM: C[m,n] = sum_k A[m,k]*B[n,k] (+bias) ---------
// Tile 128x128, BK=32 (bf16), 3-term split, double-buffered smem.
// smem stage (40960 B): Ah[128][40], Al, Bh, Bl (bf16, row stride 40 elems=80B)
template<bool BIAS>
__global__ __launch_bounds__(256, 1) void gemm_hmma(const float* __restrict__ A,
                                                    const float* __restrict__ Bw,
                                                    const float* __restrict__ bias,
                                                    float* __restrict__ Cmat,
                                                    int Ntot, int Ktot)
{
    extern __shared__ __align__(128) char smem[];
    const uint32_t sb = smem_u32(smem);
    const int tid = threadIdx.x, wid = tid >> 5, lane = tid & 31;
    const int wm = (wid & 3) * 32;      // warp m offset in tile
    const int wn = (wid >> 2) * 64;     // warp n offset in tile
    const int m0 = blockIdx.y * 128, n0 = blockIdx.x * 128;

    const int rowL = tid >> 3;          // 0..31 (loader row)
    const int c4   = tid & 7;           // 0..7  (loader float4 group)

    float acc[2][8][4];
#pragma unroll
    for (int t = 0; t < 2; t++)
#pragma unroll
        for (int j = 0; j < 8; j++)
#pragma unroll
            for (int q = 0; q < 4; q++) acc[t][j][q] = 0.f;

    float4 ra[4], rb[4];
    const int NIT = Ktot >> 5;

    auto loadTile = [&](int it) {
        const int k0 = it << 5;
#pragma unroll
        for (int i = 0; i < 4; i++) {
            ra[i] = *(const float4*)(A  + (size_t)(m0 + rowL + 32*i) * Ktot + k0 + c4*4);
            rb[i] = *(const float4*)(Bw + (size_t)(n0 + rowL + 32*i) * Ktot + k0 + c4*4);
        }
    };
    auto storeTile = [&](int stg) {
        const uint32_t base = (uint32_t)stg * 40960u;
#pragma unroll
        for (int i = 0; i < 4; i++) {
            uint32_t ro = (uint32_t)(rowL + 32*i) * 80u + (uint32_t)c4 * 8u;
            store_split(smem, base + ro,           base + 10240u + ro, ra[i]);
            store_split(smem, base + 20480u + ro,  base + 30720u + ro, rb[i]);
        }
    };

    // per-thread ldmatrix offsets
    const uint32_t lrow = (uint32_t)(lane & 15);
    const uint32_t lcol = (uint32_t)((lane >> 4) << 4);   // 0 or 16 bytes (k half)
    const uint32_t aOff = ((uint32_t)wm + lrow) * 80u + lcol;
    const uint32_t bOff = ((uint32_t)wn + lrow) * 80u + lcol;

    auto compute = [&](int stg) {
        const uint32_t base = sb + (uint32_t)stg * 40960u;
#pragma unroll
        for (int ks = 0; ks < 2; ks++) {
            const uint32_t kb = (uint32_t)ks * 32u;
            uint32_t Ahf[2][4], Alf[2][4];
#pragma unroll
            for (int t = 0; t < 2; t++) {
                ldsm4(Ahf[t], base + aOff + (uint32_t)t*1280u + kb);
                ldsm4(Alf[t], base + 10240u + aOff + (uint32_t)t*1280u + kb);
            }
#pragma unroll
            for (int ng = 0; ng < 4; ng++) {
                uint32_t Bh4[4], Bl4[4];
                ldsm4(Bh4, base + 20480u + bOff + (uint32_t)ng*1280u + kb);
                ldsm4(Bl4, base + 30720u + bOff + (uint32_t)ng*1280u + kb);
                uint32_t bh0[2] = {Bh4[0], Bh4[2]}, bh1[2] = {Bh4[1], Bh4[3]};
                uint32_t bl0[2] = {Bl4[0], Bl4[2]}, bl1[2] = {Bl4[1], Bl4[3]};
#pragma unroll
                for (int t = 0; t < 2; t++) {
                    mma_bf16(acc[t][2*ng],   Ahf[t], bh0);
                    mma_bf16(acc[t][2*ng],   Ahf[t], bl0);
                    mma_bf16(acc[t][2*ng],   Alf[t], bh0);
                    mma_bf16(acc[t][2*ng+1], Ahf[t], bh1);
                    mma_bf16(acc[t][2*ng+1], Ahf[t], bl1);
                    mma_bf16(acc[t][2*ng+1], Alf[t], bh1);
                }
            }
        }
    };

    // ---- software pipeline ----
    loadTile(0);
    storeTile(0);
    if (NIT > 1) loadTile(1);
    __syncthreads();
    for (int it = 0; it < NIT; it++) {
        compute(it & 1);
        if (it + 1 < NIT) {
            storeTile((it + 1) & 1);
            if (it + 2 < NIT) loadTile(it + 2);
        }
        __syncthreads();
    }

    // ---- epilogue ----
#pragma unroll
    for (int t = 0; t < 2; t++) {
        const int row0 = m0 + wm + t*16 + (lane >> 2);
#pragma unroll
        for (int j = 0; j < 8; j++) {
            const int col = n0 + wn + j*8 + (lane & 3)*2;
            float2 v0 = make_float2(acc[t][j][0], acc[t][j][1]);
            float2 v1 = make_float2(acc[t][j][2], acc[t][j][3]);
            if (BIAS) {
                float b0 = bias[col], b1 = bias[col+1];
                v0.x += b0; v0.y += b1; v1.x += b0; v1.y += b1;
            }
            *(float2*)(Cmat + (size_t)row0 * Ntot + col)       = v0;
            *(float2*)(Cmat + (size_t)(row0+8) * Ntot + col)   = v1;
        }
    }
}

// ---------------- RoPE (interleaved) + scatter to (b,h,s,d) ------------------
__global__ void rope_scatter(const float* __restrict__ qkv,
                             const float* __restrict__ cosb,
                             const float* __restrict__ sinb)
{
    int idx = blockIdx.x * blockDim.x + threadIdx.x;
    const int PAIRS = MTOT * (N1 / 2);
    if (idx >= PAIRS) return;
    int m     = idx / (N1 / 2);
    int pc    = (idx - m * (N1 / 2)) * 2;
    int which = pc / CH;
    int c     = pc - which * CH;
    int h     = c / HDIM;
    int d     = c - h * HDIM;
    int b     = m >> 11, s = m & (SEQ - 1);
    const float scale = 0.10206207261596575f;          // 96^-0.5

    float2 x = *(const float2*)(qkv + (size_t)m * N1 + pc);
    size_t o = ((size_t)(b * NH + h) * SEQ + s) * HDIM + d;
    if (which == 2) {
        *(float2*)(g_v + o) = x;
    } else {
        float cs = cosb[s * HDIM + d];
        float sn = sinb[s * HDIM + d];
        float2 y;
        y.x = x.x * cs - x.y * sn;
        y.y = x.y * cs + x.x * sn;
        if (which == 0) { y.x *= scale; y.y *= scale; *(float2*)(g_q + o) = y; }
        else            { *(float2*)(g_k + o) = y; }
    }
}

// ---------------- flash attention: BM=BN=128, HD=96, fp32, f32x2 -------------
__global__ __launch_bounds__(256, 1) void flash_attn(float* __restrict__ ctx)
{
    extern __shared__ float sm[];
    float* sQ = sm;                  // 96*132
    float* sK = sQ + 96 * 132;
    float* sV = sK + 96 * 132;       // 128*100
    float* sS = sV + 128 * 100;      // 128*132

    const int tid = threadIdx.x;
    const int tx  = tid & 15, ty = tid >> 4;
    const int bh  = blockIdx.y;
    const int q0  = blockIdx.x * 128;
    const float NEG_INF = __int_as_float(0xff800000);

    const float* Qg = g_q + ((size_t)bh * SEQ + q0) * HDIM;
#pragma unroll
    for (int i = 0; i < 12; i++) {
        int idx = tid + i * 256;
        int r   = idx / 24;
        int c4  = (idx - r * 24) * 4;
        float4 v = *(const float4*)(Qg + r * HDIM + c4);
        sQ[(c4+0)*132 + r] = v.x;
        sQ[(c4+1)*132 + r] = v.y;
        sQ[(c4+2)*132 + r] = v.z;
        sQ[(c4+3)*132 + r] = v.w;
    }

    float mrow[8], lrow[8];
#pragma unroll
    for (int i = 0; i < 8; i++) { mrow[i] = NEG_INF; lrow[i] = 0.f; }

    u64 o2[8][3];
#pragma unroll
    for (int i = 0; i < 8; i++)
#pragma unroll
        for (int j = 0; j < 3; j++) o2[i][j] = 0ull;

    for (int t = 0; t < SEQ / 128; t++) {
        __syncthreads();
        const float* Kg = g_k + ((size_t)bh * SEQ + t * 128) * HDIM;
        const float* Vg = g_v + ((size_t)bh * SEQ + t * 128) * HDIM;
#pragma unroll
        for (int i = 0; i < 12; i++) {
            int idx = tid + i * 256;
            int r   = idx / 24;
            int c4  = (idx - r * 24) * 4;
            float4 vk = *(const float4*)(Kg + r * HDIM + c4);
            sK[(c4+0)*132 + r] = vk.x;
            sK[(c4+1)*132 + r] = vk.y;
            sK[(c4+2)*132 + r] = vk.z;
            sK[(c4+3)*132 + r] = vk.w;
            float4 vv = *(const float4*)(Vg + r * HDIM + c4);
            *(float4*)(sV + r * 100 + c4) = vv;
        }
        __syncthreads();

        u64 s2[8][4];
#pragma unroll
        for (int i = 0; i < 8; i++)
#pragma unroll
            for (int j = 0; j < 4; j++) s2[i][j] = 0ull;

#pragma unroll 4
        for (int d = 0; d < HDIM; d++) {
            float a[8];
            *(float4*)&a[0] = *(const float4*)&sQ[d*132 + ty*8];
            *(float4*)&a[4] = *(const float4*)&sQ[d*132 + ty*8 + 4];
            ulonglong2 b01 = *(const ulonglong2*)&sK[d*132 + tx*8];
            ulonglong2 b23 = *(const ulonglong2*)&sK[d*132 + tx*8 + 4];
            u64 b2[4]; b2[0] = b01.x; b2[1] = b01.y; b2[2] = b23.x; b2[3] = b23.y;
#pragma unroll
            for (int i = 0; i < 8; i++) {
                u64 a2 = pack2(a[i]);
#pragma unroll
                for (int j = 0; j < 4; j++) ffma2(s2[i][j], a2, b2[j]);
            }
        }

        float s[8][8];
#pragma unroll
        for (int i = 0; i < 8; i++) {
#pragma unroll
            for (int j = 0; j < 4; j++) {
                float2 p = unpack2(s2[i][j]);
                s[i][2*j] = p.x; s[i][2*j+1] = p.y;
            }
        }
        float corr[8];
#pragma unroll
        for (int i = 0; i < 8; i++) {
            float rm = s[i][0];
#pragma unroll
            for (int j = 1; j < 8; j++) rm = fmaxf(rm, s[i][j]);
            rm = fmaxf(rm, __shfl_xor_sync(0xffffffffu, rm, 1));
            rm = fmaxf(rm, __shfl_xor_sync(0xffffffffu, rm, 2));
            rm = fmaxf(rm, __shfl_xor_sync(0xffffffffu, rm, 4));
            rm = fmaxf(rm, __shfl_xor_sync(0xffffffffu, rm, 8));
            float mnew = fmaxf(mrow[i], rm);
            float c = __expf(mrow[i] - mnew);
            mrow[i] = mnew;
            corr[i] = c;
            float sum = 0.f;
#pragma unroll
            for (int j = 0; j < 8; j++) {
                float p = __expf(s[i][j] - mnew);
                s[i][j] = p;
                sum += p;
            }
            sum += __shfl_xor_sync(0xffffffffu, sum, 1);
            sum += __shfl_xor_sync(0xffffffffu, sum, 2);
            sum += __shfl_xor_sync(0xffffffffu, sum, 4);
            sum += __shfl_xor_sync(0xffffffffu, sum, 8);
            lrow[i] = lrow[i] * c + sum;
        }

#pragma unroll
        for (int i = 0; i < 8; i++) {
            float4 w0 = make_float4(s[i][0], s[i][1], s[i][2], s[i][3]);
            float4 w1 = make_float4(s[i][4], s[i][5], s[i][6], s[i][7]);
            *(float4*)&sS[(ty*8+i)*132 + tx*8]     = w0;
            *(float4*)&sS[(ty*8+i)*132 + tx*8 + 4] = w1;
        }
        __syncthreads();

#pragma unroll
        for (int i = 0; i < 8; i++) {
            u64 c2 = pack2(corr[i]);
#pragma unroll
            for (int j = 0; j < 3; j++) mul2(o2[i][j], c2);
        }

#pragma unroll 2
        for (int kk = 0; kk < 128; kk++) {
            float p[8];
#pragma unroll
            for (int i = 0; i < 8; i++) p[i] = sS[(ty*8+i)*132 + kk];
            u64 v0 = *(const u64*)&sV[kk*100 + tx*6];
            u64 v1 = *(const u64*)&sV[kk*100 + tx*6 + 2];
            u64 v2 = *(const u64*)&sV[kk*100 + tx*6 + 4];
#pragma unroll
            for (int i = 0; i < 8; i++) {
                u64 a2 = pack2(p[i]);
                ffma2(o2[i][0], a2, v0);
                ffma2(o2[i][1], a2, v1);
                ffma2(o2[i][2], a2, v2);
            }
        }
    }

    const int h = bh & (NH - 1), b = bh >> 3;
#pragma unroll
    for (int i = 0; i < 8; i++) {
        int r = q0 + ty*8 + i;
        float linv = 1.f / lrow[i];
        float* dst = ctx + ((size_t)b * SEQ + r) * CH + h * HDIM + tx * 6;
        float2 a0 = unpack2(o2[i][0]);
        float2 a1 = unpack2(o2[i][1]);
        float2 a2 = unpack2(o2[i][2]);
        a0.x *= linv; a0.y *= linv; *(float2*)(dst)     = a0;
        a1.x *= linv; a1.y *= linv; *(float2*)(dst + 2) = a1;
        a2.x *= linv; a2.y *= linv; *(float2*)(dst + 4) = a2;
    }
}

// ------------------------------ launch ---------------------------------------
extern "C" void kernel_launch(void* const* d_in, const int* in_sizes, int n_in,
                              void* d_out, int out_size)
{
    const float* x     = (const float*)d_in[0];
    const float* cosb  = (const float*)d_in[1];
    const float* sinb  = (const float*)d_in[2];
    const float* Wqkv  = (const float*)d_in[3];
    const float* Wproj = (const float*)d_in[4];
    const float* bproj = (const float*)d_in[5];
    float* out = (float*)d_out;

    float *qkv, *ctx;
    cudaGetSymbolAddress((void**)&qkv, g_qkv);
    cudaGetSymbolAddress((void**)&ctx, g_ctx);

    const size_t shm_flash = (size_t)(2*96*132 + 128*100 + 128*132) * sizeof(float);
    cudaFuncSetAttribute(flash_attn, cudaFuncAttributeMaxDynamicSharedMemorySize, (int)shm_flash);
    const size_t shm_gemm = 2 * 40960;   // 81,920 B
    cudaFuncSetAttribute(gemm_hmma<false>, cudaFuncAttributeMaxDynamicSharedMemorySize, (int)shm_gemm);
    cudaFuncSetAttribute(gemm_hmma<true>,  cudaFuncAttributeMaxDynamicSharedMemorySize, (int)shm_gemm);

    // 1) qkv = x @ Wqkv^T            (8192 x 2304, K=768) — HMMA
    dim3 g1(N1 / 128, MTOT / 128);
    gemm_hmma<false><<<g1, 256, shm_gemm>>>(x, Wqkv, nullptr, qkv, N1, CH);

    // 2) RoPE + scatter to (b,h,s,d); q pre-scaled
    int pairs = MTOT * (N1 / 2);
    rope_scatter<<<(pairs + 255) / 256, 256>>>(qkv, cosb, sinb);

    // 3) flash attention -> ctx (b,s,C)
    dim3 g2(SEQ / 128, Bq * NH);
    flash_attn<<<g2, 256, shm_flash>>>(ctx);

    // 4) out = ctx @ Wproj^T + bproj (8192 x 768, K=768) — HMMA
    dim3 g3(CH / 128, MTOT / 128);
    gemm_hmma<true><<<g3, 256, shm_gemm>>>(ctx, Wproj, bproj, out, CH, CH);
}

// round 5
// speedup vs baseline: 2.5922x; 1.9900x over previous
#include <cuda_runtime.h>
#include <cuda_bf16.h>
#include <cstdint>

#define Bq   4
#define SEQ  2048
#define CH   768
#define NH   8
#define HDIM 96
#define MTOT (Bq*SEQ)     /* 8192 */
#define N1   (3*CH)       /* 2304 */

// ---- HMMA helpers (baseline PTX, sm_80+) -------------------------------------
__device__ __forceinline__ uint32_t smem_u32(const void* p) {
    uint32_t a;
    asm("{ .reg .u64 t; cvta.to.shared.u64 t, %1; cvt.u32.u64 %0, t; }" : "=r"(a) : "l"(p));
    return a;
}
__device__ __forceinline__ void ldsm4(uint32_t* r, uint32_t addr) {
    asm volatile("ldmatrix.sync.aligned.m8n8.x4.shared.b16 {%0,%1,%2,%3}, [%4];"
        : "=r"(r[0]), "=r"(r[1]), "=r"(r[2]), "=r"(r[3]) : "r"(addr));
}
__device__ __forceinline__ void ldsm4t(uint32_t* r, uint32_t addr) {
    asm volatile("ldmatrix.sync.aligned.m8n8.x4.trans.shared.b16 {%0,%1,%2,%3}, [%4];"
        : "=r"(r[0]), "=r"(r[1]), "=r"(r[2]), "=r"(r[3]) : "r"(addr));
}
__device__ __forceinline__ void mma_bf16(float* d, const uint32_t* a, const uint32_t* b) {
    asm volatile("mma.sync.aligned.m16n8k16.row.col.f32.bf16.bf16.f32 "
        "{%0,%1,%2,%3}, {%4,%5,%6,%7}, {%8,%9}, {%0,%1,%2,%3};"
        : "+f"(d[0]), "+f"(d[1]), "+f"(d[2]), "+f"(d[3])
        : "r"(a[0]), "r"(a[1]), "r"(a[2]), "r"(a[3]), "r"(b[0]), "r"(b[1]));
}
// hi = truncated bf16 pair; lo = rn residual pair
__device__ __forceinline__ uint32_t hi_pair(float x, float y) {
    return __byte_perm(__float_as_uint(x), __float_as_uint(y), 0x7632);
}
__device__ __forceinline__ uint32_t lo_pair(float x, float y) {
    float lx = x - __uint_as_float(__float_as_uint(x) & 0xffff0000u);
    float ly = y - __uint_as_float(__float_as_uint(y) & 0xffff0000u);
    uint32_t r;
    asm("cvt.rn.bf16x2.f32 %0, %1, %2;" : "=r"(r) : "f"(ly), "f"(lx));
    return r;
}

// ---------------- scratch (static __device__, no allocations) ----------------
__device__ float g_qkv[(size_t)MTOT * N1];                 // 75.5 MB
__device__ __nv_bfloat16 g_qh[(size_t)Bq*NH*SEQ*HDIM];     // split bf16 (b,h,s,d)
__device__ __nv_bfloat16 g_ql[(size_t)Bq*NH*SEQ*HDIM];
__device__ __nv_bfloat16 g_kh[(size_t)Bq*NH*SEQ*HDIM];
__device__ __nv_bfloat16 g_kl[(size_t)Bq*NH*SEQ*HDIM];
__device__ __nv_bfloat16 g_vh[(size_t)Bq*NH*SEQ*HDIM];
__device__ __nv_bfloat16 g_vl[(size_t)Bq*NH*SEQ*HDIM];
__device__ float g_ctx[(size_t)MTOT * CH];                 // 25 MB, (b,s,C)

// ---- fp32 -> (hi,lo) bf16 split, 4 elems, 8B each ----------------------------
__device__ __forceinline__ void store_split(char* smem, uint32_t offH, uint32_t offL, float4 v) {
    uint2 hi;
    hi.x = hi_pair(v.x, v.y);
    hi.y = hi_pair(v.z, v.w);
    uint2 lo;
    lo.x = lo_pair(v.x, v.y);
    lo.y = lo_pair(v.z, v.w);
    *(uint2*)(smem + offH) = hi;
    *(uint2*)(smem + offL) = lo;
}

// ---------------- HMMA NT GEMM (unchanged from R4) ----------------------------
template<bool BIAS>
__global__ __launch_bounds__(256, 1) void gemm_hmma(const float* __restrict__ A,
                                                    const float* __restrict__ Bw,
                                                    const float* __restrict__ bias,
                                                    float* __restrict__ Cmat,
                                                    int Ntot, int Ktot)
{
    extern __shared__ __align__(128) char smem[];
    const uint32_t sb = smem_u32(smem);
    const int tid = threadIdx.x, wid = tid >> 5, lane = tid & 31;
    const int wm = (wid & 3) * 32;
    const int wn = (wid >> 2) * 64;
    const int m0 = blockIdx.y * 128, n0 = blockIdx.x * 128;

    const int rowL = tid >> 3;
    const int c4   = tid & 7;

    float acc[2][8][4];
#pragma unroll
    for (int t = 0; t < 2; t++)
#pragma unroll
        for (int j = 0; j < 8; j++)
#pragma unroll
            for (int q = 0; q < 4; q++) acc[t][j][q] = 0.f;

    float4 ra[4], rb[4];
    const int NIT = Ktot >> 5;

    auto loadTile = [&](int it) {
        const int k0 = it << 5;
#pragma unroll
        for (int i = 0; i < 4; i++) {
            ra[i] = *(const float4*)(A  + (size_t)(m0 + rowL + 32*i) * Ktot + k0 + c4*4);
            rb[i] = *(const float4*)(Bw + (size_t)(n0 + rowL + 32*i) * Ktot + k0 + c4*4);
        }
    };
    auto storeTile = [&](int stg) {
        const uint32_t base = (uint32_t)stg * 40960u;
#pragma unroll
        for (int i = 0; i < 4; i++) {
            uint32_t ro = (uint32_t)(rowL + 32*i) * 80u + (uint32_t)c4 * 8u;
            store_split(smem, base + ro,           base + 10240u + ro, ra[i]);
            store_split(smem, base + 20480u + ro,  base + 30720u + ro, rb[i]);
        }
    };

    const uint32_t lrow = (uint32_t)(lane & 15);
    const uint32_t lcol = (uint32_t)((lane >> 4) << 4);
    const uint32_t aOff = ((uint32_t)wm + lrow) * 80u + lcol;
    const uint32_t bOff = ((uint32_t)wn + lrow) * 80u + lcol;

    auto compute = [&](int stg) {
        const uint32_t base = sb + (uint32_t)stg * 40960u;
#pragma unroll
        for (int ks = 0; ks < 2; ks++) {
            const uint32_t kb = (uint32_t)ks * 32u;
            uint32_t Ahf[2][4], Alf[2][4];
#pragma unroll
            for (int t = 0; t < 2; t++) {
                ldsm4(Ahf[t], base + aOff + (uint32_t)t*1280u + kb);
                ldsm4(Alf[t], base + 10240u + aOff + (uint32_t)t*1280u + kb);
            }
#pragma unroll
            for (int ng = 0; ng < 4; ng++) {
                uint32_t Bh4[4], Bl4[4];
                ldsm4(Bh4, base + 20480u + bOff + (uint32_t)ng*1280u + kb);
                ldsm4(Bl4, base + 30720u + bOff + (uint32_t)ng*1280u + kb);
                uint32_t bh0[2] = {Bh4[0], Bh4[2]}, bh1[2] = {Bh4[1], Bh4[3]};
                uint32_t bl0[2] = {Bl4[0], Bl4[2]}, bl1[2] = {Bl4[1], Bl4[3]};
#pragma unroll
                for (int t = 0; t < 2; t++) {
                    mma_bf16(acc[t][2*ng],   Ahf[t], bh0);
                    mma_bf16(acc[t][2*ng],   Ahf[t], bl0);
                    mma_bf16(acc[t][2*ng],   Alf[t], bh0);
                    mma_bf16(acc[t][2*ng+1], Ahf[t], bh1);
                    mma_bf16(acc[t][2*ng+1], Ahf[t], bl1);
                    mma_bf16(acc[t][2*ng+1], Alf[t], bh1);
                }
            }
        }
    };

    loadTile(0);
    storeTile(0);
    if (NIT > 1) loadTile(1);
    __syncthreads();
    for (int it = 0; it < NIT; it++) {
        compute(it & 1);
        if (it + 1 < NIT) {
            storeTile((it + 1) & 1);
            if (it + 2 < NIT) loadTile(it + 2);
        }
        __syncthreads();
    }

#pragma unroll
    for (int t = 0; t < 2; t++) {
        const int row0 = m0 + wm + t*16 + (lane >> 2);
#pragma unroll
        for (int j = 0; j < 8; j++) {
            const int col = n0 + wn + j*8 + (lane & 3)*2;
            float2 v0 = make_float2(acc[t][j][0], acc[t][j][1]);
            float2 v1 = make_float2(acc[t][j][2], acc[t][j][3]);
            if (BIAS) {
                float b0 = bias[col], b1 = bias[col+1];
                v0.x += b0; v0.y += b1; v1.x += b0; v1.y += b1;
            }
            *(float2*)(Cmat + (size_t)row0 * Ntot + col)       = v0;
            *(float2*)(Cmat + (size_t)(row0+8) * Ntot + col)   = v1;
        }
    }
}

// ---------------- RoPE + scatter to pre-split bf16 (b,h,s,d) ------------------
__global__ void rope_scatter(const float* __restrict__ qkv,
                             const float* __restrict__ cosb,
                             const float* __restrict__ sinb)
{
    int idx = blockIdx.x * blockDim.x + threadIdx.x;
    const int PAIRS = MTOT * (N1 / 2);
    if (idx >= PAIRS) return;
    int m     = idx / (N1 / 2);
    int pc    = (idx - m * (N1 / 2)) * 2;
    int which = pc / CH;
    int c     = pc - which * CH;
    int h     = c / HDIM;
    int d     = c - h * HDIM;
    int b     = m >> 11, s = m & (SEQ - 1);
    const float scale = 0.10206207261596575f;          // 96^-0.5

    float2 x = *(const float2*)(qkv + (size_t)m * N1 + pc);
    size_t o = ((size_t)(b * NH + h) * SEQ + s) * HDIM + d;
    float2 y;
    if (which == 2) {
        y = x;
    } else {
        float cs = cosb[s * HDIM + d];
        float sn = sinb[s * HDIM + d];
        y.x = x.x * cs - x.y * sn;
        y.y = x.y * cs + x.x * sn;
        if (which == 0) { y.x *= scale; y.y *= scale; }
    }
    uint32_t hi = hi_pair(y.x, y.y);
    uint32_t lo = lo_pair(y.x, y.y);
    __nv_bfloat16* dh = (which == 0) ? g_qh : (which == 1) ? g_kh : g_vh;
    __nv_bfloat16* dl = (which == 0) ? g_ql : (which == 1) ? g_kl : g_vl;
    *(uint32_t*)(dh + o) = hi;
    *(uint32_t*)(dl + o) = lo;
}

// ---------------- flash attention, HMMA, 3-term bf16 split --------------------
// 8 warps; warp w owns Q rows [w*16, w*16+16). Row stride 208 B (conflict-free).
#define RS 208u
__global__ __launch_bounds__(256, 1) void flash_hmma(float* __restrict__ ctx)
{
    extern __shared__ __align__(128) char sm[];
    const uint32_t sb = smem_u32(sm);
    const uint32_t QH = 0, QL = 26624, KH = 53248, KL = 79872, VH = 106496, VL = 133120;

    const int tid = threadIdx.x, wid = tid >> 5, lane = tid & 31;
    const int bh = blockIdx.y;
    const int q0 = blockIdx.x * 128;
    const float NEG_INF = __int_as_float(0xff800000);

    const uint32_t lrow = (uint32_t)(lane & 15);
    const uint32_t lgrp = (uint32_t)(lane >> 4);

    // ---- load Q (hi/lo) ----
    {
        const char* qh = (const char*)(g_qh + ((size_t)bh * SEQ + q0) * HDIM);
        const char* ql = (const char*)(g_ql + ((size_t)bh * SEQ + q0) * HDIM);
#pragma unroll
        for (int i = 0; i < 6; i++) {
            int idx = tid + i * 256;
            int r = idx / 12, g = idx % 12;
            uint32_t so = (uint32_t)r * RS + (uint32_t)g * 16u;
            *(uint4*)(sm + QH + so) = *(const uint4*)(qh + r * 192 + g * 16);
            *(uint4*)(sm + QL + so) = *(const uint4*)(ql + r * 192 + g * 16);
        }
    }

    float m0 = NEG_INF, m1 = NEG_INF, l0 = 0.f, l1 = 0.f;
    float o[12][4];
#pragma unroll
    for (int j = 0; j < 12; j++)
#pragma unroll
        for (int q = 0; q < 4; q++) o[j][q] = 0.f;

    const uint32_t aOff = ((uint32_t)(wid * 16) + lrow) * RS + lgrp * 16u;

    for (int t = 0; t < SEQ / 128; t++) {
        __syncthreads();
        // ---- load K,V (hi/lo) tile ----
        {
            const size_t base = ((size_t)bh * SEQ + t * 128) * HDIM;
            const char* kh = (const char*)(g_kh + base);
            const char* kl = (const char*)(g_kl + base);
            const char* vh = (const char*)(g_vh + base);
            const char* vl = (const char*)(g_vl + base);
#pragma unroll
            for (int i = 0; i < 6; i++) {
                int idx = tid + i * 256;
                int r = idx / 12, g = idx % 12;
                uint32_t so = (uint32_t)r * RS + (uint32_t)g * 16u;
                int go = r * 192 + g * 16;
                *(uint4*)(sm + KH + so) = *(const uint4*)(kh + go);
                *(uint4*)(sm + KL + so) = *(const uint4*)(kl + go);
                *(uint4*)(sm + VH + so) = *(const uint4*)(vh + go);
                *(uint4*)(sm + VL + so) = *(const uint4*)(vl + go);
            }
        }
        __syncthreads();

        // ---- S = Q K^T : 16 n8 tiles, fp32 acc ----
        float sacc[16][4];
#pragma unroll
        for (int j = 0; j < 16; j++)
#pragma unroll
            for (int q = 0; q < 4; q++) sacc[j][q] = 0.f;

#pragma unroll
        for (int ks = 0; ks < 6; ks++) {
            const uint32_t kb = (uint32_t)ks * 32u;
            uint32_t Ah[4], Al[4];
            ldsm4(Ah, sb + QH + aOff + kb);
            ldsm4(Al, sb + QL + aOff + kb);
#pragma unroll
            for (int n2 = 0; n2 < 8; n2++) {
                const uint32_t bo = ((uint32_t)(n2 * 16) + lrow) * RS + lgrp * 16u + kb;
                uint32_t Bh4[4], Bl4[4];
                ldsm4(Bh4, sb + KH + bo);
                ldsm4(Bl4, sb + KL + bo);
                uint32_t bh0[2] = {Bh4[0], Bh4[2]}, bh1[2] = {Bh4[1], Bh4[3]};
                uint32_t bl0[2] = {Bl4[0], Bl4[2]}, bl1[2] = {Bl4[1], Bl4[3]};
                mma_bf16(sacc[2*n2],   Ah, bh0);
                mma_bf16(sacc[2*n2],   Ah, bl0);
                mma_bf16(sacc[2*n2],   Al, bh0);
                mma_bf16(sacc[2*n2+1], Ah, bh1);
                mma_bf16(sacc[2*n2+1], Ah, bl1);
                mma_bf16(sacc[2*n2+1], Al, bh1);
            }
        }

        // ---- online softmax in registers (rows r and r+8) ----
        float mx0 = NEG_INF, mx1 = NEG_INF;
#pragma unroll
        for (int j = 0; j < 16; j++) {
            mx0 = fmaxf(mx0, fmaxf(sacc[j][0], sacc[j][1]));
            mx1 = fmaxf(mx1, fmaxf(sacc[j][2], sacc[j][3]));
        }
        mx0 = fmaxf(mx0, __shfl_xor_sync(0xffffffffu, mx0, 1));
        mx0 = fmaxf(mx0, __shfl_xor_sync(0xffffffffu, mx0, 2));
        mx1 = fmaxf(mx1, __shfl_xor_sync(0xffffffffu, mx1, 1));
        mx1 = fmaxf(mx1, __shfl_xor_sync(0xffffffffu, mx1, 2));
        float mn0 = fmaxf(m0, mx0), mn1 = fmaxf(m1, mx1);
        float c0 = __expf(m0 - mn0), c1 = __expf(m1 - mn1);
        m0 = mn0; m1 = mn1;
        float s0 = 0.f, s1 = 0.f;
#pragma unroll
        for (int j = 0; j < 16; j++) {
            float p0 = __expf(sacc[j][0] - mn0);
            float p1 = __expf(sacc[j][1] - mn0);
            float p2 = __expf(sacc[j][2] - mn1);
            float p3 = __expf(sacc[j][3] - mn1);
            sacc[j][0] = p0; sacc[j][1] = p1; sacc[j][2] = p2; sacc[j][3] = p3;
            s0 += p0 + p1; s1 += p2 + p3;
        }
        s0 += __shfl_xor_sync(0xffffffffu, s0, 1);
        s0 += __shfl_xor_sync(0xffffffffu, s0, 2);
        s1 += __shfl_xor_sync(0xffffffffu, s1, 1);
        s1 += __shfl_xor_sync(0xffffffffu, s1, 2);
        l0 = l0 * c0 + s0;
        l1 = l1 * c1 + s1;

        // ---- rescale O ----
#pragma unroll
        for (int j = 0; j < 12; j++) {
            o[j][0] *= c0; o[j][1] *= c0; o[j][2] *= c1; o[j][3] *= c1;
        }

        // ---- O += P V : A frags repacked from sacc, V via ldmatrix.trans ----
#pragma unroll
        for (int k2 = 0; k2 < 8; k2++) {
            uint32_t aH[4], aL[4];
            const int ta = 2 * k2, tb = 2 * k2 + 1;
            aH[0] = hi_pair(sacc[ta][0], sacc[ta][1]);
            aH[1] = hi_pair(sacc[ta][2], sacc[ta][3]);
            aH[2] = hi_pair(sacc[tb][0], sacc[tb][1]);
            aH[3] = hi_pair(sacc[tb][2], sacc[tb][3]);
            aL[0] = lo_pair(sacc[ta][0], sacc[ta][1]);
            aL[1] = lo_pair(sacc[ta][2], sacc[ta][3]);
            aL[2] = lo_pair(sacc[tb][0], sacc[tb][1]);
            aL[3] = lo_pair(sacc[tb][2], sacc[tb][3]);
#pragma unroll
            for (int dg = 0; dg < 6; dg++) {
                const uint32_t vo = ((uint32_t)(k2 * 16) + lrow) * RS + (uint32_t)dg * 32u + lgrp * 16u;
                uint32_t Vh4[4], Vl4[4];
                ldsm4t(Vh4, sb + VH + vo);
                ldsm4t(Vl4, sb + VL + vo);
                uint32_t vh0[2] = {Vh4[0], Vh4[1]}, vh1[2] = {Vh4[2], Vh4[3]};
                uint32_t vl0[2] = {Vl4[0], Vl4[1]}, vl1[2] = {Vl4[2], Vl4[3]};
                mma_bf16(o[2*dg],   aH, vh0);
                mma_bf16(o[2*dg],   aH, vl0);
                mma_bf16(o[2*dg],   aL, vh0);
                mma_bf16(o[2*dg+1], aH, vh1);
                mma_bf16(o[2*dg+1], aH, vl1);
                mma_bf16(o[2*dg+1], aL, vh1);
            }
        }
    }

    // ---- epilogue: ctx[b, s, h*96 + d] = o / l ----
    const int h = bh & (NH - 1), b = bh >> 3;
    const float i0 = 1.f / l0, i1 = 1.f / l1;
    const int r0 = q0 + wid * 16 + (lane >> 2);
    float* base0 = ctx + ((size_t)b * SEQ + r0) * CH + h * HDIM + (lane & 3) * 2;
    float* base1 = base0 + (size_t)8 * CH;
#pragma unroll
    for (int j = 0; j < 12; j++) {
        *(float2*)(base0 + j * 8) = make_float2(o[j][0] * i0, o[j][1] * i0);
        *(float2*)(base1 + j * 8) = make_float2(o[j][2] * i1, o[j][3] * i1);
    }
}

// ------------------------------ launch ---------------------------------------
extern "C" void kernel_launch(void* const* d_in, const int* in_sizes, int n_in,
                              void* d_out, int out_size)
{
    const float* x     = (const float*)d_in[0];
    const float* cosb  = (const float*)d_in[1];
    const float* sinb  = (const float*)d_in[2];
    const float* Wqkv  = (const float*)d_in[3];
    const float* Wproj = (const float*)d_in[4];
    const float* bproj = (const float*)d_in[5];
    float* out = (float*)d_out;

    float *qkv, *ctx;
    cudaGetSymbolAddress((void**)&qkv, g_qkv);
    cudaGetSymbolAddress((void**)&ctx, g_ctx);

    const size_t shm_gemm = 2 * 40960;       // 81,920 B
    cudaFuncSetAttribute(gemm_hmma<false>, cudaFuncAttributeMaxDynamicSharedMemorySize, (int)shm_gemm);
    cudaFuncSetAttribute(gemm_hmma<true>,  cudaFuncAttributeMaxDynamicSharedMemorySize, (int)shm_gemm);
    const size_t shm_flash = 159744;         // 6 x 128 x 208 B
    cudaFuncSetAttribute(flash_hmma, cudaFuncAttributeMaxDynamicSharedMemorySize, (int)shm_flash);

    // 1) qkv = x @ Wqkv^T            (8192 x 2304, K=768) — HMMA
    dim3 g1(N1 / 128, MTOT / 128);
    gemm_hmma<false><<<g1, 256, shm_gemm>>>(x, Wqkv, nullptr, qkv, N1, CH);

    // 2) RoPE + scatter to pre-split bf16 (b,h,s,d); q pre-scaled
    int pairs = MTOT * (N1 / 2);
    rope_scatter<<<(pairs + 255) / 256, 256>>>(qkv, cosb, sinb);

    // 3) flash attention (HMMA) -> ctx (b,s,C)
    dim3 g2(SEQ / 128, Bq * NH);
    flash_hmma<<<g2, 256, shm_flash>>>(ctx);

    // 4) out = ctx @ Wproj^T + bproj (8192 x 768, K=768) — HMMA
    dim3 g3(CH / 128, MTOT / 128);
    gemm_hmma<true><<<g3, 256, shm_gemm>>>(ctx, Wproj, bproj, out, CH, CH);
}

// round 6
// speedup vs baseline: 2.6777x; 1.0330x over previous
#include <cuda_runtime.h>
#include <cuda_bf16.h>
#include <cstdint>

#define Bq   4
#define SEQ  2048
#define CH   768
#define NH   8
#define HDIM 96
#define MTOT (Bq*SEQ)     /* 8192 */
#define N1   (3*CH)       /* 2304 */

// ---- HMMA helpers (baseline PTX, sm_80+) -------------------------------------
__device__ __forceinline__ uint32_t smem_u32(const void* p) {
    uint32_t a;
    asm("{ .reg .u64 t; cvta.to.shared.u64 t, %1; cvt.u32.u64 %0, t; }" : "=r"(a) : "l"(p));
    return a;
}
__device__ __forceinline__ void ldsm4(uint32_t* r, uint32_t addr) {
    asm volatile("ldmatrix.sync.aligned.m8n8.x4.shared.b16 {%0,%1,%2,%3}, [%4];"
        : "=r"(r[0]), "=r"(r[1]), "=r"(r[2]), "=r"(r[3]) : "r"(addr));
}
__device__ __forceinline__ void ldsm4t(uint32_t* r, uint32_t addr) {
    asm volatile("ldmatrix.sync.aligned.m8n8.x4.trans.shared.b16 {%0,%1,%2,%3}, [%4];"
        : "=r"(r[0]), "=r"(r[1]), "=r"(r[2]), "=r"(r[3]) : "r"(addr));
}
__device__ __forceinline__ void mma_bf16(float* d, const uint32_t* a, const uint32_t* b) {
    asm volatile("mma.sync.aligned.m16n8k16.row.col.f32.bf16.bf16.f32 "
        "{%0,%1,%2,%3}, {%4,%5,%6,%7}, {%8,%9}, {%0,%1,%2,%3};"
        : "+f"(d[0]), "+f"(d[1]), "+f"(d[2]), "+f"(d[3])
        : "r"(a[0]), "r"(a[1]), "r"(a[2]), "r"(a[3]), "r"(b[0]), "r"(b[1]));
}
__device__ __forceinline__ uint32_t hi_pair(float x, float y) {
    return __byte_perm(__float_as_uint(x), __float_as_uint(y), 0x7632);
}
__device__ __forceinline__ uint32_t lo_pair(float x, float y) {
    float lx = x - __uint_as_float(__float_as_uint(x) & 0xffff0000u);
    float ly = y - __uint_as_float(__float_as_uint(y) & 0xffff0000u);
    uint32_t r;
    asm("cvt.rn.bf16x2.f32 %0, %1, %2;" : "=r"(r) : "f"(ly), "f"(lx));
    return r;
}
// ---- cp.async -----------------------------------------------------------------
__device__ __forceinline__ void cp16(uint32_t saddr, const void* g) {
    asm volatile("cp.async.cg.shared.global [%0], [%1], 16;" :: "r"(saddr), "l"(g));
}
__device__ __forceinline__ void cp_commit() { asm volatile("cp.async.commit_group;" ::: "memory"); }
template<int N> __device__ __forceinline__ void cp_wait() {
    asm volatile("cp.async.wait_group %0;" :: "n"(N) : "memory");
}

// ---------------- scratch (static __device__, no allocations) ----------------
__device__ __nv_bfloat16 g_xh[(size_t)MTOT*CH],  g_xl[(size_t)MTOT*CH];
__device__ __nv_bfloat16 g_wqh[(size_t)N1*CH],   g_wql[(size_t)N1*CH];
__device__ __nv_bfloat16 g_wph[(size_t)CH*CH],   g_wpl[(size_t)CH*CH];
__device__ __nv_bfloat16 g_qh[(size_t)MTOT*HDIM*NH/NH*NH];  // (b,h,s,d) = MTOT*HDIM*... size MTOT*96? actually Bq*NH*SEQ*HDIM
__device__ __nv_bfloat16 g_ql[(size_t)Bq*NH*SEQ*HDIM];
__device__ __nv_bfloat16 g_kh[(size_t)Bq*NH*SEQ*HDIM];
__device__ __nv_bfloat16 g_kl[(size_t)Bq*NH*SEQ*HDIM];
__device__ __nv_bfloat16 g_vh[(size_t)Bq*NH*SEQ*HDIM];
__device__ __nv_bfloat16 g_vl[(size_t)Bq*NH*SEQ*HDIM];
__device__ __nv_bfloat16 g_ch[(size_t)MTOT*CH],  g_cl[(size_t)MTOT*CH];

// ---------------- split inputs once: fp32 -> bf16 hi/lo ----------------------
__global__ void split_all(const float* __restrict__ x,
                          const float* __restrict__ wq,
                          const float* __restrict__ wp)
{
    const int NX = MTOT*CH/4, NQ = N1*CH/4, NP = CH*CH/4;
    int i = blockIdx.x * blockDim.x + threadIdx.x;
    const float* src; __nv_bfloat16 *dh, *dl; int j;
    if (i < NX)                { src = x;  dh = g_xh;  dl = g_xl;  j = i; }
    else if (i < NX + NQ)      { src = wq; dh = g_wqh; dl = g_wql; j = i - NX; }
    else if (i < NX + NQ + NP) { src = wp; dh = g_wph; dl = g_wpl; j = i - NX - NQ; }
    else return;
    float4 v = ((const float4*)src)[j];
    uint2 hi = make_uint2(hi_pair(v.x, v.y), hi_pair(v.z, v.w));
    uint2 lo = make_uint2(lo_pair(v.x, v.y), lo_pair(v.z, v.w));
    ((uint2*)dh)[j] = hi;
    ((uint2*)dl)[j] = lo;
}

// ---------------- bf16-input HMMA NT GEMM, cp.async 4-stage pipeline ----------
// Tile 128x128, BK=32. smem stage 32KB: Ah(8K) Al Bh Bl; row 64B, XOR chunk swizzle.
// EPI: 0 = rope-scatter to split q/k/v; 1 = bias + fp32 store.
__device__ __forceinline__ uint32_t swz(int r, int c) {   // byte offset of 16B chunk
    return (uint32_t)(r * 64 + ((c ^ ((r >> 1) & 3)) << 4));
}

template<int EPI>
__global__ __launch_bounds__(256, 1) void gemm_bf16(const __nv_bfloat16* __restrict__ Ah_g,
                                                    const __nv_bfloat16* __restrict__ Al_g,
                                                    const __nv_bfloat16* __restrict__ Bh_g,
                                                    const __nv_bfloat16* __restrict__ Bl_g,
                                                    const float* __restrict__ aux0,   // cos | bias
                                                    const float* __restrict__ aux1,   // sin | null
                                                    float* __restrict__ Cmat,
                                                    int Ntot, int Ktot)
{
    extern __shared__ __align__(128) char smem[];
    const uint32_t sb = smem_u32(smem);
    const int tid = threadIdx.x, wid = tid >> 5, lane = tid & 31;
    const int wm = (wid & 3) * 32;
    const int wn = (wid >> 2) * 64;
    const int m0 = blockIdx.y * 128, n0 = blockIdx.x * 128;

    float acc[2][8][4];
#pragma unroll
    for (int t = 0; t < 2; t++)
#pragma unroll
        for (int j = 0; j < 8; j++)
#pragma unroll
            for (int q = 0; q < 4; q++) acc[t][j][q] = 0.f;

    const int NIT = Ktot >> 5;   // 24
    const int chR = tid >> 2, chC = tid & 3;     // loader: row 0..63(+64), chunk 0..3

    auto produce = [&](int it) {
        const uint32_t base = sb + (uint32_t)(it & 3) * 32768u;
        const int k0 = it << 5;
#pragma unroll
        for (int u = 0; u < 2; u++) {
            int r = chR + u * 64;
            uint32_t sw = swz(r, chC);
            size_t goA = (size_t)(m0 + r) * Ktot + k0 + chC * 8;
            size_t goB = (size_t)(n0 + r) * Ktot + k0 + chC * 8;
            cp16(base + sw,          Ah_g + goA);
            cp16(base + 8192u + sw,  Al_g + goA);
            cp16(base + 16384u + sw, Bh_g + goB);
            cp16(base + 24576u + sw, Bl_g + goB);
        }
        cp_commit();
    };

    const int lrow = lane & 15, lgrp = lane >> 4;

    auto compute = [&](int stg) {
        const uint32_t base = sb + (uint32_t)stg * 32768u;
#pragma unroll
        for (int ks = 0; ks < 2; ks++) {
            const int c = 2 * ks + lgrp;
            uint32_t Ahf[2][4], Alf[2][4];
#pragma unroll
            for (int t = 0; t < 2; t++) {
                int r = wm + t * 16 + lrow;
                uint32_t sw = swz(r, c);
                ldsm4(Ahf[t], base + sw);
                ldsm4(Alf[t], base + 8192u + sw);
            }
#pragma unroll
            for (int ng = 0; ng < 4; ng++) {
                int r = wn + ng * 16 + lrow;
                uint32_t sw = swz(r, c);
                uint32_t Bh4[4], Bl4[4];
                ldsm4(Bh4, base + 16384u + sw);
                ldsm4(Bl4, base + 24576u + sw);
                uint32_t bh0[2] = {Bh4[0], Bh4[2]}, bh1[2] = {Bh4[1], Bh4[3]};
                uint32_t bl0[2] = {Bl4[0], Bl4[2]}, bl1[2] = {Bl4[1], Bl4[3]};
#pragma unroll
                for (int t = 0; t < 2; t++) {
                    mma_bf16(acc[t][2*ng],   Ahf[t], bh0);
                    mma_bf16(acc[t][2*ng],   Ahf[t], bl0);
                    mma_bf16(acc[t][2*ng],   Alf[t], bh0);
                    mma_bf16(acc[t][2*ng+1], Ahf[t], bh1);
                    mma_bf16(acc[t][2*ng+1], Ahf[t], bl1);
                    mma_bf16(acc[t][2*ng+1], Alf[t], bh1);
                }
            }
        }
    };

    produce(0); produce(1); produce(2);
    for (int it = 0; it < NIT; it++) {
        cp_wait<2>();
        __syncthreads();
        if (it + 3 < NIT) produce(it + 3);
        compute(it & 3);
    }

    // ---- epilogue ----
    if (EPI == 1) {
#pragma unroll
        for (int t = 0; t < 2; t++) {
            const int row0 = m0 + wm + t*16 + (lane >> 2);
#pragma unroll
            for (int j = 0; j < 8; j++) {
                const int col = n0 + wn + j*8 + (lane & 3)*2;
                float b0 = aux0[col], b1 = aux0[col+1];
                *(float2*)(Cmat + (size_t)row0 * Ntot + col) =
                    make_float2(acc[t][j][0] + b0, acc[t][j][1] + b1);
                *(float2*)(Cmat + (size_t)(row0+8) * Ntot + col) =
                    make_float2(acc[t][j][2] + b0, acc[t][j][3] + b1);
            }
        }
    } else {
        // rope + scatter to split bf16 q/k/v, layout (b,h,s,d)
        const float scale = 0.10206207261596575f;   // 96^-0.5
#pragma unroll
        for (int t = 0; t < 2; t++) {
            const int rowA = m0 + wm + t*16 + (lane >> 2);
#pragma unroll
            for (int j = 0; j < 8; j++) {
                const int col = n0 + wn + j*8 + (lane & 3)*2;   // even
                const int which = col / CH;
                const int cc = col - which * CH;
                const int h = cc / HDIM;
                const int d = cc - h * HDIM;
#pragma unroll
                for (int half = 0; half < 2; half++) {
                    const int m = rowA + half * 8;
                    const int s = m & (SEQ - 1), b = m >> 11;
                    float e = acc[t][j][2*half], o = acc[t][j][2*half+1];
                    float2 y;
                    if (which == 2) {
                        y = make_float2(e, o);
                    } else {
                        float cs = aux0[s * HDIM + d];
                        float sn = aux1[s * HDIM + d];
                        y.x = e * cs - o * sn;
                        y.y = o * cs + e * sn;
                        if (which == 0) { y.x *= scale; y.y *= scale; }
                    }
                    size_t off = ((size_t)(b * NH + h) * SEQ + s) * HDIM + d;
                    uint32_t hi = hi_pair(y.x, y.y);
                    uint32_t lo = lo_pair(y.x, y.y);
                    __nv_bfloat16* dh = (which == 0) ? g_qh : (which == 1) ? g_kh : g_vh;
                    __nv_bfloat16* dl = (which == 0) ? g_ql : (which == 1) ? g_kl : g_vl;
                    *(uint32_t*)(dh + off) = hi;
                    *(uint32_t*)(dl + off) = lo;
                }
            }
        }
    }
}

// ---------------- flash attention, HMMA, 3-term bf16 split --------------------
#define RS 208u
__global__ __launch_bounds__(256, 1) void flash_hmma()
{
    extern __shared__ __align__(128) char sm[];
    const uint32_t sb = smem_u32(sm);
    const uint32_t QH = 0, QL = 26624, KH = 53248, KL = 79872, VH = 106496, VL = 133120;

    const int tid = threadIdx.x, wid = tid >> 5, lane = tid & 31;
    const int bh = blockIdx.y;
    const int q0 = blockIdx.x * 128;
    const float NEG_INF = __int_as_float(0xff800000);

    const uint32_t lrow = (uint32_t)(lane & 15);
    const uint32_t lgrp = (uint32_t)(lane >> 4);

    {
        const char* qh = (const char*)(g_qh + ((size_t)bh * SEQ + q0) * HDIM);
        const char* ql = (const char*)(g_ql + ((size_t)bh * SEQ + q0) * HDIM);
#pragma unroll
        for (int i = 0; i < 6; i++) {
            int idx = tid + i * 256;
            int r = idx / 12, g = idx % 12;
            uint32_t so = (uint32_t)r * RS + (uint32_t)g * 16u;
            *(uint4*)(sm + QH + so) = *(const uint4*)(qh + r * 192 + g * 16);
            *(uint4*)(sm + QL + so) = *(const uint4*)(ql + r * 192 + g * 16);
        }
    }

    float m0 = NEG_INF, m1 = NEG_INF, l0 = 0.f, l1 = 0.f;
    float o[12][4];
#pragma unroll
    for (int j = 0; j < 12; j++)
#pragma unroll
        for (int q = 0; q < 4; q++) o[j][q] = 0.f;

    const uint32_t aOff = ((uint32_t)(wid * 16) + lrow) * RS + lgrp * 16u;

    for (int t = 0; t < SEQ / 128; t++) {
        __syncthreads();
        {
            const size_t base = ((size_t)bh * SEQ + t * 128) * HDIM;
            const char* kh = (const char*)(g_kh + base);
            const char* kl = (const char*)(g_kl + base);
            const char* vh = (const char*)(g_vh + base);
            const char* vl = (const char*)(g_vl + base);
#pragma unroll
            for (int i = 0; i < 6; i++) {
                int idx = tid + i * 256;
                int r = idx / 12, g = idx % 12;
                uint32_t so = (uint32_t)r * RS + (uint32_t)g * 16u;
                int go = r * 192 + g * 16;
                *(uint4*)(sm + KH + so) = *(const uint4*)(kh + go);
                *(uint4*)(sm + KL + so) = *(const uint4*)(kl + go);
                *(uint4*)(sm + VH + so) = *(const uint4*)(vh + go);
                *(uint4*)(sm + VL + so) = *(const uint4*)(vl + go);
            }
        }
        __syncthreads();

        float sacc[16][4];
#pragma unroll
        for (int j = 0; j < 16; j++)
#pragma unroll
            for (int q = 0; q < 4; q++) sacc[j][q] = 0.f;

#pragma unroll
        for (int ks = 0; ks < 6; ks++) {
            const uint32_t kb = (uint32_t)ks * 32u;
            uint32_t Ah[4], Al[4];
            ldsm4(Ah, sb + QH + aOff + kb);
            ldsm4(Al, sb + QL + aOff + kb);
#pragma unroll
            for (int n2 = 0; n2 < 8; n2++) {
                const uint32_t bo = ((uint32_t)(n2 * 16) + lrow) * RS + lgrp * 16u + kb;
                uint32_t Bh4[4], Bl4[4];
                ldsm4(Bh4, sb + KH + bo);
                ldsm4(Bl4, sb + KL + bo);
                uint32_t bh0[2] = {Bh4[0], Bh4[2]}, bh1[2] = {Bh4[1], Bh4[3]};
                uint32_t bl0[2] = {Bl4[0], Bl4[2]}, bl1[2] = {Bl4[1], Bl4[3]};
                mma_bf16(sacc[2*n2],   Ah, bh0);
                mma_bf16(sacc[2*n2],   Ah, bl0);
                mma_bf16(sacc[2*n2],   Al, bh0);
                mma_bf16(sacc[2*n2+1], Ah, bh1);
                mma_bf16(sacc[2*n2+1], Ah, bl1);
                mma_bf16(sacc[2*n2+1], Al, bh1);
            }
        }

        float mx0 = NEG_INF, mx1 = NEG_INF;
#pragma unroll
        for (int j = 0; j < 16; j++) {
            mx0 = fmaxf(mx0, fmaxf(sacc[j][0], sacc[j][1]));
            mx1 = fmaxf(mx1, fmaxf(sacc[j][2], sacc[j][3]));
        }
        mx0 = fmaxf(mx0, __shfl_xor_sync(0xffffffffu, mx0, 1));
        mx0 = fmaxf(mx0, __shfl_xor_sync(0xffffffffu, mx0, 2));
        mx1 = fmaxf(mx1, __shfl_xor_sync(0xffffffffu, mx1, 1));
        mx1 = fmaxf(mx1, __shfl_xor_sync(0xffffffffu, mx1, 2));
        float mn0 = fmaxf(m0, mx0), mn1 = fmaxf(m1, mx1);
        float c0 = __expf(m0 - mn0), c1 = __expf(m1 - mn1);
        m0 = mn0; m1 = mn1;
        float s0 = 0.f, s1 = 0.f;
#pragma unroll
        for (int j = 0; j < 16; j++) {
            float p0 = __expf(sacc[j][0] - mn0);
            float p1 = __expf(sacc[j][1] - mn0);
            float p2 = __expf(sacc[j][2] - mn1);
            float p3 = __expf(sacc[j][3] - mn1);
            sacc[j][0] = p0; sacc[j][1] = p1; sacc[j][2] = p2; sacc[j][3] = p3;
            s0 += p0 + p1; s1 += p2 + p3;
        }
        s0 += __shfl_xor_sync(0xffffffffu, s0, 1);
        s0 += __shfl_xor_sync(0xffffffffu, s0, 2);
        s1 += __shfl_xor_sync(0xffffffffu, s1, 1);
        s1 += __shfl_xor_sync(0xffffffffu, s1, 2);
        l0 = l0 * c0 + s0;
        l1 = l1 * c1 + s1;

#pragma unroll
        for (int j = 0; j < 12; j++) {
            o[j][0] *= c0; o[j][1] *= c0; o[j][2] *= c1; o[j][3] *= c1;
        }

#pragma unroll
        for (int k2 = 0; k2 < 8; k2++) {
            uint32_t aH[4], aL[4];
            const int ta = 2 * k2, tb = 2 * k2 + 1;
            aH[0] = hi_pair(sacc[ta][0], sacc[ta][1]);
            aH[1] = hi_pair(sacc[ta][2], sacc[ta][3]);
            aH[2] = hi_pair(sacc[tb][0], sacc[tb][1]);
            aH[3] = hi_pair(sacc[tb][2], sacc[tb][3]);
            aL[0] = lo_pair(sacc[ta][0], sacc[ta][1]);
            aL[1] = lo_pair(sacc[ta][2], sacc[ta][3]);
            aL[2] = lo_pair(sacc[tb][0], sacc[tb][1]);
            aL[3] = lo_pair(sacc[tb][2], sacc[tb][3]);
#pragma unroll
            for (int dg = 0; dg < 6; dg++) {
                const uint32_t vo = ((uint32_t)(k2 * 16) + lrow) * RS + (uint32_t)dg * 32u + lgrp * 16u;
                uint32_t Vh4[4], Vl4[4];
                ldsm4t(Vh4, sb + VH + vo);
                ldsm4t(Vl4, sb + VL + vo);
                uint32_t vh0[2] = {Vh4[0], Vh4[1]}, vh1[2] = {Vh4[2], Vh4[3]};
                uint32_t vl0[2] = {Vl4[0], Vl4[1]}, vl1[2] = {Vl4[2], Vl4[3]};
                mma_bf16(o[2*dg],   aH, vh0);
                mma_bf16(o[2*dg],   aH, vl0);
                mma_bf16(o[2*dg],   aL, vh0);
                mma_bf16(o[2*dg+1], aH, vh1);
                mma_bf16(o[2*dg+1], aH, vl1);
                mma_bf16(o[2*dg+1], aL, vh1);
            }
        }
    }

    // ---- epilogue: ctx split bf16: (b, s, h*96 + d) ----
    const int h = bh & (NH - 1), b = bh >> 3;
    const float i0 = 1.f / l0, i1 = 1.f / l1;
    const int r0 = q0 + wid * 16 + (lane >> 2);
    size_t base0 = ((size_t)b * SEQ + r0) * CH + h * HDIM + (lane & 3) * 2;
    size_t base1 = base0 + (size_t)8 * CH;
#pragma unroll
    for (int j = 0; j < 12; j++) {
        float a0 = o[j][0] * i0, a1 = o[j][1] * i0;
        float b0 = o[j][2] * i1, b1 = o[j][3] * i1;
        *(uint32_t*)(g_ch + base0 + j * 8) = hi_pair(a0, a1);
        *(uint32_t*)(g_cl + base0 + j * 8) = lo_pair(a0, a1);
        *(uint32_t*)(g_ch + base1 + j * 8) = hi_pair(b0, b1);
        *(uint32_t*)(g_cl + base1 + j * 8) = lo_pair(b0, b1);
    }
}

// ------------------------------ launch ---------------------------------------
extern "C" void kernel_launch(void* const* d_in, const int* in_sizes, int n_in,
                              void* d_out, int out_size)
{
    const float* x     = (const float*)d_in[0];
    const float* cosb  = (const float*)d_in[1];
    const float* sinb  = (const float*)d_in[2];
    const float* Wqkv  = (const float*)d_in[3];
    const float* Wproj = (const float*)d_in[4];
    const float* bproj = (const float*)d_in[5];
    float* out = (float*)d_out;

    const size_t shm_gemm = 4 * 32768;       // 131,072 B
    cudaFuncSetAttribute(gemm_bf16<0>, cudaFuncAttributeMaxDynamicSharedMemorySize, (int)shm_gemm);
    cudaFuncSetAttribute(gemm_bf16<1>, cudaFuncAttributeMaxDynamicSharedMemorySize, (int)shm_gemm);
    const size_t shm_flash = 159744;         // 6 x 128 x 208 B
    cudaFuncSetAttribute(flash_hmma, cudaFuncAttributeMaxDynamicSharedMemorySize, (int)shm_flash);

    // 0) split x, Wqkv, Wproj -> bf16 hi/lo
    {
        int quads = (MTOT*CH + N1*CH + CH*CH) / 4;
        split_all<<<(quads + 255) / 256, 256>>>(x, Wqkv, Wproj);
    }

    // 1) qkv GEMM + fused rope scatter (8192 x 2304, K=768)
    {
        __nv_bfloat16 *xh, *xl, *wqh, *wql;
        cudaGetSymbolAddress((void**)&xh,  g_xh);
        cudaGetSymbolAddress((void**)&xl,  g_xl);
        cudaGetSymbolAddress((void**)&wqh, g_wqh);
        cudaGetSymbolAddress((void**)&wql, g_wql);
        dim3 g1(N1 / 128, MTOT / 128);
        gemm_bf16<0><<<g1, 256, shm_gemm>>>(xh, xl, wqh, wql, cosb, sinb, nullptr, N1, CH);
    }

    // 2) flash attention (HMMA) -> split ctx
    {
        dim3 g2(SEQ / 128, Bq * NH);
        flash_hmma<<<g2, 256, shm_flash>>>();
    }

    // 3) out = ctx @ Wproj^T + bproj (8192 x 768, K=768)
    {
        __nv_bfloat16 *ch, *cl, *wph, *wpl;
        cudaGetSymbolAddress((void**)&ch,  g_ch);
        cudaGetSymbolAddress((void**)&cl,  g_cl);
        cudaGetSymbolAddress((void**)&wph, g_wph);
        cudaGetSymbolAddress((void**)&wpl, g_wpl);
        dim3 g3(CH / 128, MTOT / 128);
        gemm_bf16<1><<<g3, 256, shm_gemm>>>(ch, cl, wph, wpl, bproj, nullptr, out, CH, CH);
    }
}

// round 7
// speedup vs baseline: 2.9635x; 1.1067x over previous
#include <cuda_runtime.h>
#include <cuda_bf16.h>
#include <cstdint>

#define Bq   4
#define SEQ  2048
#define CH   768
#define NH   8
#define HDIM 96
#define MTOT (Bq*SEQ)     /* 8192 */
#define N1   (3*CH)       /* 2304 */

// ---- HMMA helpers (baseline PTX, sm_80+) -------------------------------------
__device__ __forceinline__ uint32_t smem_u32(const void* p) {
    uint32_t a;
    asm("{ .reg .u64 t; cvta.to.shared.u64 t, %1; cvt.u32.u64 %0, t; }" : "=r"(a) : "l"(p));
    return a;
}
__device__ __forceinline__ void ldsm4(uint32_t* r, uint32_t addr) {
    asm volatile("ldmatrix.sync.aligned.m8n8.x4.shared.b16 {%0,%1,%2,%3}, [%4];"
        : "=r"(r[0]), "=r"(r[1]), "=r"(r[2]), "=r"(r[3]) : "r"(addr));
}
__device__ __forceinline__ void ldsm4t(uint32_t* r, uint32_t addr) {
    asm volatile("ldmatrix.sync.aligned.m8n8.x4.trans.shared.b16 {%0,%1,%2,%3}, [%4];"
        : "=r"(r[0]), "=r"(r[1]), "=r"(r[2]), "=r"(r[3]) : "r"(addr));
}
__device__ __forceinline__ void mma_bf16(float* d, const uint32_t* a, const uint32_t* b) {
    asm volatile("mma.sync.aligned.m16n8k16.row.col.f32.bf16.bf16.f32 "
        "{%0,%1,%2,%3}, {%4,%5,%6,%7}, {%8,%9}, {%0,%1,%2,%3};"
        : "+f"(d[0]), "+f"(d[1]), "+f"(d[2]), "+f"(d[3])
        : "r"(a[0]), "r"(a[1]), "r"(a[2]), "r"(a[3]), "r"(b[0]), "r"(b[1]));
}
__device__ __forceinline__ uint32_t hi_pair(float x, float y) {
    return __byte_perm(__float_as_uint(x), __float_as_uint(y), 0x7632);
}
__device__ __forceinline__ uint32_t lo_pair(float x, float y) {
    float lx = x - __uint_as_float(__float_as_uint(x) & 0xffff0000u);
    float ly = y - __uint_as_float(__float_as_uint(y) & 0xffff0000u);
    uint32_t r;
    asm("cvt.rn.bf16x2.f32 %0, %1, %2;" : "=r"(r) : "f"(ly), "f"(lx));
    return r;
}
// ---- cp.async -----------------------------------------------------------------
__device__ __forceinline__ void cp16(uint32_t saddr, const void* g) {
    asm volatile("cp.async.cg.shared.global [%0], [%1], 16;" :: "r"(saddr), "l"(g));
}
__device__ __forceinline__ void cp_commit() { asm volatile("cp.async.commit_group;" ::: "memory"); }
template<int N> __device__ __forceinline__ void cp_wait() {
    asm volatile("cp.async.wait_group %0;" :: "n"(N) : "memory");
}

// ---------------- scratch (static __device__, no allocations) ----------------
__device__ __nv_bfloat16 g_xh[(size_t)MTOT*CH],  g_xl[(size_t)MTOT*CH];
__device__ __nv_bfloat16 g_wqh[(size_t)N1*CH],   g_wql[(size_t)N1*CH];
__device__ __nv_bfloat16 g_wph[(size_t)CH*CH],   g_wpl[(size_t)CH*CH];
__device__ __nv_bfloat16 g_qh[(size_t)Bq*NH*SEQ*HDIM];
__device__ __nv_bfloat16 g_ql[(size_t)Bq*NH*SEQ*HDIM];
__device__ __nv_bfloat16 g_kh[(size_t)Bq*NH*SEQ*HDIM];
__device__ __nv_bfloat16 g_kl[(size_t)Bq*NH*SEQ*HDIM];
__device__ __nv_bfloat16 g_vh[(size_t)Bq*NH*SEQ*HDIM];
__device__ __nv_bfloat16 g_vl[(size_t)Bq*NH*SEQ*HDIM];
__device__ __nv_bfloat16 g_ch[(size_t)MTOT*CH],  g_cl[(size_t)MTOT*CH];

// ---------------- split inputs once: fp32 -> bf16 hi/lo ----------------------
__global__ void split_all(const float* __restrict__ x,
                          const float* __restrict__ wq,
                          const float* __restrict__ wp)
{
    const int NX = MTOT*CH/4, NQ = N1*CH/4, NP = CH*CH/4;
    int i = blockIdx.x * blockDim.x + threadIdx.x;
    const float* src; __nv_bfloat16 *dh, *dl; int j;
    if (i < NX)                { src = x;  dh = g_xh;  dl = g_xl;  j = i; }
    else if (i < NX + NQ)      { src = wq; dh = g_wqh; dl = g_wql; j = i - NX; }
    else if (i < NX + NQ + NP) { src = wp; dh = g_wph; dl = g_wpl; j = i - NX - NQ; }
    else return;
    float4 v = ((const float4*)src)[j];
    uint2 hi = make_uint2(hi_pair(v.x, v.y), hi_pair(v.z, v.w));
    uint2 lo = make_uint2(lo_pair(v.x, v.y), lo_pair(v.z, v.w));
    ((uint2*)dh)[j] = hi;
    ((uint2*)dl)[j] = lo;
}

// ---------------- bf16-input HMMA NT GEMM, cp.async 3-stage, occ 2 ------------
__device__ __forceinline__ uint32_t swz(int r, int c) {   // byte offset of 16B chunk
    return (uint32_t)(r * 64 + ((c ^ ((r >> 1) & 3)) << 4));
}

template<int EPI>
__global__ __launch_bounds__(256, 2) void gemm_bf16(const __nv_bfloat16* __restrict__ Ah_g,
                                                    const __nv_bfloat16* __restrict__ Al_g,
                                                    const __nv_bfloat16* __restrict__ Bh_g,
                                                    const __nv_bfloat16* __restrict__ Bl_g,
                                                    const float* __restrict__ aux0,   // cos | bias
                                                    const float* __restrict__ aux1,   // sin | null
                                                    float* __restrict__ Cmat,
                                                    int Ntot, int Ktot)
{
    extern __shared__ __align__(128) char smem[];
    const uint32_t sb = smem_u32(smem);
    const int tid = threadIdx.x, wid = tid >> 5, lane = tid & 31;
    const int wm = (wid & 3) * 32;
    const int wn = (wid >> 2) * 64;
    const int m0 = blockIdx.y * 128, n0 = blockIdx.x * 128;

    float acc[2][8][4];
#pragma unroll
    for (int t = 0; t < 2; t++)
#pragma unroll
        for (int j = 0; j < 8; j++)
#pragma unroll
            for (int q = 0; q < 4; q++) acc[t][j][q] = 0.f;

    const int NIT = Ktot >> 5;   // 24
    const int chR = tid >> 2, chC = tid & 3;

    auto produce = [&](int it) {
        const uint32_t base = sb + (uint32_t)(it % 3) * 32768u;
        const int k0 = it << 5;
#pragma unroll
        for (int u = 0; u < 2; u++) {
            int r = chR + u * 64;
            uint32_t sw = swz(r, chC);
            size_t goA = (size_t)(m0 + r) * Ktot + k0 + chC * 8;
            size_t goB = (size_t)(n0 + r) * Ktot + k0 + chC * 8;
            cp16(base + sw,          Ah_g + goA);
            cp16(base + 8192u + sw,  Al_g + goA);
            cp16(base + 16384u + sw, Bh_g + goB);
            cp16(base + 24576u + sw, Bl_g + goB);
        }
        cp_commit();
    };

    const int lrow = lane & 15, lgrp = lane >> 4;

    auto compute = [&](int stg) {
        const uint32_t base = sb + (uint32_t)stg * 32768u;
#pragma unroll
        for (int ks = 0; ks < 2; ks++) {
            const int c = 2 * ks + lgrp;
            uint32_t Ahf[2][4], Alf[2][4];
#pragma unroll
            for (int t = 0; t < 2; t++) {
                int r = wm + t * 16 + lrow;
                uint32_t sw = swz(r, c);
                ldsm4(Ahf[t], base + sw);
                ldsm4(Alf[t], base + 8192u + sw);
            }
#pragma unroll
            for (int ng = 0; ng < 4; ng++) {
                int r = wn + ng * 16 + lrow;
                uint32_t sw = swz(r, c);
                uint32_t Bh4[4], Bl4[4];
                ldsm4(Bh4, base + 16384u + sw);
                ldsm4(Bl4, base + 24576u + sw);
                uint32_t bh0[2] = {Bh4[0], Bh4[2]}, bh1[2] = {Bh4[1], Bh4[3]};
                uint32_t bl0[2] = {Bl4[0], Bl4[2]}, bl1[2] = {Bl4[1], Bl4[3]};
#pragma unroll
                for (int t = 0; t < 2; t++) {
                    mma_bf16(acc[t][2*ng],   Ahf[t], bh0);
                    mma_bf16(acc[t][2*ng],   Ahf[t], bl0);
                    mma_bf16(acc[t][2*ng],   Alf[t], bh0);
                    mma_bf16(acc[t][2*ng+1], Ahf[t], bh1);
                    mma_bf16(acc[t][2*ng+1], Ahf[t], bl1);
                    mma_bf16(acc[t][2*ng+1], Alf[t], bh1);
                }
            }
        }
    };

    produce(0); produce(1);
    for (int it = 0; it < NIT; it++) {
        cp_wait<1>();
        __syncthreads();
        if (it + 2 < NIT) produce(it + 2);
        compute(it % 3);
    }

    // ---- epilogue ----
    if (EPI == 1) {
#pragma unroll
        for (int t = 0; t < 2; t++) {
            const int row0 = m0 + wm + t*16 + (lane >> 2);
#pragma unroll
            for (int j = 0; j < 8; j++) {
                const int col = n0 + wn + j*8 + (lane & 3)*2;
                float b0 = aux0[col], b1 = aux0[col+1];
                *(float2*)(Cmat + (size_t)row0 * Ntot + col) =
                    make_float2(acc[t][j][0] + b0, acc[t][j][1] + b1);
                *(float2*)(Cmat + (size_t)(row0+8) * Ntot + col) =
                    make_float2(acc[t][j][2] + b0, acc[t][j][3] + b1);
            }
        }
    } else {
        const float scale = 0.10206207261596575f;   // 96^-0.5
#pragma unroll
        for (int t = 0; t < 2; t++) {
            const int rowA = m0 + wm + t*16 + (lane >> 2);
#pragma unroll
            for (int j = 0; j < 8; j++) {
                const int col = n0 + wn + j*8 + (lane & 3)*2;   // even
                const int which = col / CH;
                const int cc = col - which * CH;
                const int h = cc / HDIM;
                const int d = cc - h * HDIM;
#pragma unroll
                for (int half = 0; half < 2; half++) {
                    const int m = rowA + half * 8;
                    const int s = m & (SEQ - 1), b = m >> 11;
                    float e = acc[t][j][2*half], o = acc[t][j][2*half+1];
                    float2 y;
                    if (which == 2) {
                        y = make_float2(e, o);
                    } else {
                        float cs = aux0[s * HDIM + d];
                        float sn = aux1[s * HDIM + d];
                        y.x = e * cs - o * sn;
                        y.y = o * cs + e * sn;
                        if (which == 0) { y.x *= scale; y.y *= scale; }
                    }
                    size_t off = ((size_t)(b * NH + h) * SEQ + s) * HDIM + d;
                    uint32_t hi = hi_pair(y.x, y.y);
                    uint32_t lo = lo_pair(y.x, y.y);
                    __nv_bfloat16* dh = (which == 0) ? g_qh : (which == 1) ? g_kh : g_vh;
                    __nv_bfloat16* dl = (which == 0) ? g_ql : (which == 1) ? g_kl : g_vl;
                    *(uint32_t*)(dh + off) = hi;
                    *(uint32_t*)(dl + off) = lo;
                }
            }
        }
    }
}

// ---------------- flash attention: Q in regs, cp.async double-buffered KV -----
// smem: 2 stages x (KH,KL,VH,VL) each 128 x RS bytes. Stage = 106496 B.
#define RS   208u
#define TSZ  26624u
__global__ __launch_bounds__(256, 1) void flash_hmma()
{
    extern __shared__ __align__(128) char sm[];
    const uint32_t sb = smem_u32(sm);

    const int tid = threadIdx.x, wid = tid >> 5, lane = tid & 31;
    const int bh = blockIdx.y;
    const int q0 = blockIdx.x * 128;
    const float NEG_INF = __int_as_float(0xff800000);

    const uint32_t lrow = (uint32_t)(lane & 15);
    const uint32_t lgrp = (uint32_t)(lane >> 4);

    // ---- stage Q into smem (stage 0 area), ldsm to registers, then reuse ----
    uint32_t qH[6][4], qL[6][4];
    {
        const char* qh = (const char*)(g_qh + ((size_t)bh * SEQ + q0) * HDIM);
        const char* ql = (const char*)(g_ql + ((size_t)bh * SEQ + q0) * HDIM);
#pragma unroll
        for (int i = 0; i < 6; i++) {
            int idx = tid + i * 256;
            int r = idx / 12, g = idx % 12;
            uint32_t so = (uint32_t)r * RS + (uint32_t)g * 16u;
            *(uint4*)(sm + so)       = *(const uint4*)(qh + r * 192 + g * 16);
            *(uint4*)(sm + TSZ + so) = *(const uint4*)(ql + r * 192 + g * 16);
        }
        __syncthreads();
        const uint32_t aOff = ((uint32_t)(wid * 16) + lrow) * RS + lgrp * 16u;
#pragma unroll
        for (int ks = 0; ks < 6; ks++) {
            ldsm4(qH[ks], sb + aOff + (uint32_t)ks * 32u);
            ldsm4(qL[ks], sb + TSZ + aOff + (uint32_t)ks * 32u);
        }
        __syncthreads();
    }

    float m0 = NEG_INF, m1 = NEG_INF, l0 = 0.f, l1 = 0.f;
    float o[12][4];
#pragma unroll
    for (int j = 0; j < 12; j++)
#pragma unroll
        for (int q = 0; q < 4; q++) o[j][q] = 0.f;

    const int ldR = tid / 12 - ((tid / 12) >= 21 ? 21 : 0);  // unused fallback (kept simple below)

    auto produce = [&](int t) {
        const uint32_t base = sb + (uint32_t)(t & 1) * (4u * TSZ);
        const size_t gbase = ((size_t)bh * SEQ + t * 128) * HDIM;
        const char* kh = (const char*)(g_kh + gbase);
        const char* kl = (const char*)(g_kl + gbase);
        const char* vh = (const char*)(g_vh + gbase);
        const char* vl = (const char*)(g_vl + gbase);
#pragma unroll
        for (int i = 0; i < 6; i++) {
            int idx = tid + i * 256;
            int r = idx / 12, g = idx % 12;
            uint32_t so = (uint32_t)r * RS + (uint32_t)g * 16u;
            int go = r * 192 + g * 16;
            cp16(base + so,            kh + go);
            cp16(base + TSZ + so,      kl + go);
            cp16(base + 2u*TSZ + so,   vh + go);
            cp16(base + 3u*TSZ + so,   vl + go);
        }
        cp_commit();
    };

    produce(0);

    for (int t = 0; t < SEQ / 128; t++) {
        cp_wait<0>();
        __syncthreads();
        if (t + 1 < SEQ / 128) produce(t + 1);

        const uint32_t base = sb + (uint32_t)(t & 1) * (4u * TSZ);

        // ---- S = Q K^T ----
        float sacc[16][4];
#pragma unroll
        for (int j = 0; j < 16; j++)
#pragma unroll
            for (int q = 0; q < 4; q++) sacc[j][q] = 0.f;

#pragma unroll
        for (int ks = 0; ks < 6; ks++) {
            const uint32_t kb = (uint32_t)ks * 32u;
#pragma unroll
            for (int n2 = 0; n2 < 8; n2++) {
                const uint32_t bo = ((uint32_t)(n2 * 16) + lrow) * RS + lgrp * 16u + kb;
                uint32_t Bh4[4], Bl4[4];
                ldsm4(Bh4, base + bo);
                ldsm4(Bl4, base + TSZ + bo);
                uint32_t bh0[2] = {Bh4[0], Bh4[2]}, bh1[2] = {Bh4[1], Bh4[3]};
                uint32_t bl0[2] = {Bl4[0], Bl4[2]}, bl1[2] = {Bl4[1], Bl4[3]};
                mma_bf16(sacc[2*n2],   qH[ks], bh0);
                mma_bf16(sacc[2*n2],   qH[ks], bl0);
                mma_bf16(sacc[2*n2],   qL[ks], bh0);
                mma_bf16(sacc[2*n2+1], qH[ks], bh1);
                mma_bf16(sacc[2*n2+1], qH[ks], bl1);
                mma_bf16(sacc[2*n2+1], qL[ks], bh1);
            }
        }

        // ---- online softmax in registers ----
        float mx0 = NEG_INF, mx1 = NEG_INF;
#pragma unroll
        for (int j = 0; j < 16; j++) {
            mx0 = fmaxf(mx0, fmaxf(sacc[j][0], sacc[j][1]));
            mx1 = fmaxf(mx1, fmaxf(sacc[j][2], sacc[j][3]));
        }
        mx0 = fmaxf(mx0, __shfl_xor_sync(0xffffffffu, mx0, 1));
        mx0 = fmaxf(mx0, __shfl_xor_sync(0xffffffffu, mx0, 2));
        mx1 = fmaxf(mx1, __shfl_xor_sync(0xffffffffu, mx1, 1));
        mx1 = fmaxf(mx1, __shfl_xor_sync(0xffffffffu, mx1, 2));
        float mn0 = fmaxf(m0, mx0), mn1 = fmaxf(m1, mx1);
        float c0 = __expf(m0 - mn0), c1 = __expf(m1 - mn1);
        m0 = mn0; m1 = mn1;
        float s0 = 0.f, s1 = 0.f;
#pragma unroll
        for (int j = 0; j < 16; j++) {
            float p0 = __expf(sacc[j][0] - mn0);
            float p1 = __expf(sacc[j][1] - mn0);
            float p2 = __expf(sacc[j][2] - mn1);
            float p3 = __expf(sacc[j][3] - mn1);
            sacc[j][0] = p0; sacc[j][1] = p1; sacc[j][2] = p2; sacc[j][3] = p3;
            s0 += p0 + p1; s1 += p2 + p3;
        }
        s0 += __shfl_xor_sync(0xffffffffu, s0, 1);
        s0 += __shfl_xor_sync(0xffffffffu, s0, 2);
        s1 += __shfl_xor_sync(0xffffffffu, s1, 1);
        s1 += __shfl_xor_sync(0xffffffffu, s1, 2);
        l0 = l0 * c0 + s0;
        l1 = l1 * c1 + s1;

#pragma unroll
        for (int j = 0; j < 12; j++) {
            o[j][0] *= c0; o[j][1] *= c0; o[j][2] *= c1; o[j][3] *= c1;
        }

        // ---- O += P V ----
#pragma unroll
        for (int k2 = 0; k2 < 8; k2++) {
            uint32_t aH[4], aL[4];
            const int ta = 2 * k2, tb = 2 * k2 + 1;
            aH[0] = hi_pair(sacc[ta][0], sacc[ta][1]);
            aH[1] = hi_pair(sacc[ta][2], sacc[ta][3]);
            aH[2] = hi_pair(sacc[tb][0], sacc[tb][1]);
            aH[3] = hi_pair(sacc[tb][2], sacc[tb][3]);
            aL[0] = lo_pair(sacc[ta][0], sacc[ta][1]);
            aL[1] = lo_pair(sacc[ta][2], sacc[ta][3]);
            aL[2] = lo_pair(sacc[tb][0], sacc[tb][1]);
            aL[3] = lo_pair(sacc[tb][2], sacc[tb][3]);
#pragma unroll
            for (int dg = 0; dg < 6; dg++) {
                const uint32_t vo = ((uint32_t)(k2 * 16) + lrow) * RS + (uint32_t)dg * 32u + lgrp * 16u;
                uint32_t Vh4[4], Vl4[4];
                ldsm4t(Vh4, base + 2u*TSZ + vo);
                ldsm4t(Vl4, base + 3u*TSZ + vo);
                uint32_t vh0[2] = {Vh4[0], Vh4[1]}, vh1[2] = {Vh4[2], Vh4[3]};
                uint32_t vl0[2] = {Vl4[0], Vl4[1]}, vl1[2] = {Vl4[2], Vl4[3]};
                mma_bf16(o[2*dg],   aH, vh0);
                mma_bf16(o[2*dg],   aH, vl0);
                mma_bf16(o[2*dg],   aL, vh0);
                mma_bf16(o[2*dg+1], aH, vh1);
                mma_bf16(o[2*dg+1], aH, vl1);
                mma_bf16(o[2*dg+1], aL, vh1);
            }
        }
        __syncthreads();   // all warps done reading stage before next produce overwrites? (next produce targets other stage; this guards t+2 issued next iter)
    }

    // ---- epilogue: ctx split bf16: (b, s, h*96 + d) ----
    const int h = bh & (NH - 1), b = bh >> 3;
    const float i0 = 1.f / l0, i1 = 1.f / l1;
    const int r0 = q0 + wid * 16 + (lane >> 2);
    size_t base0 = ((size_t)b * SEQ + r0) * CH + h * HDIM + (lane & 3) * 2;
    size_t base1 = base0 + (size_t)8 * CH;
#pragma unroll
    for (int j = 0; j < 12; j++) {
        float a0 = o[j][0] * i0, a1 = o[j][1] * i0;
        float b0 = o[j][2] * i1, b1 = o[j][3] * i1;
        *(uint32_t*)(g_ch + base0 + j * 8) = hi_pair(a0, a1);
        *(uint32_t*)(g_cl + base0 + j * 8) = lo_pair(a0, a1);
        *(uint32_t*)(g_ch + base1 + j * 8) = hi_pair(b0, b1);
        *(uint32_t*)(g_cl + base1 + j * 8) = lo_pair(b0, b1);
    }
}

// ------------------------------ launch ---------------------------------------
extern "C" void kernel_launch(void* const* d_in, const int* in_sizes, int n_in,
                              void* d_out, int out_size)
{
    const float* x     = (const float*)d_in[0];
    const float* cosb  = (const float*)d_in[1];
    const float* sinb  = (const float*)d_in[2];
    const float* Wqkv  = (const float*)d_in[3];
    const float* Wproj = (const float*)d_in[4];
    const float* bproj = (const float*)d_in[5];
    float* out = (float*)d_out;

    const size_t shm_gemm = 3 * 32768;       // 98,304 B -> 2 CTAs/SM
    cudaFuncSetAttribute(gemm_bf16<0>, cudaFuncAttributeMaxDynamicSharedMemorySize, (int)shm_gemm);
    cudaFuncSetAttribute(gemm_bf16<1>, cudaFuncAttributeMaxDynamicSharedMemorySize, (int)shm_gemm);
    const size_t shm_flash = 2 * 4 * 26624;  // 212,992 B
    cudaFuncSetAttribute(flash_hmma, cudaFuncAttributeMaxDynamicSharedMemorySize, (int)shm_flash);

    // 0) split x, Wqkv, Wproj -> bf16 hi/lo
    {
        int quads = (MTOT*CH + N1*CH + CH*CH) / 4;
        split_all<<<(quads + 255) / 256, 256>>>(x, Wqkv, Wproj);
    }

    // 1) qkv GEMM + fused rope scatter (8192 x 2304, K=768)
    {
        __nv_bfloat16 *xh, *xl, *wqh, *wql;
        cudaGetSymbolAddress((void**)&xh,  g_xh);
        cudaGetSymbolAddress((void**)&xl,  g_xl);
        cudaGetSymbolAddress((void**)&wqh, g_wqh);
        cudaGetSymbolAddress((void**)&wql, g_wql);
        dim3 g1(N1 / 128, MTOT / 128);
        gemm_bf16<0><<<g1, 256, shm_gemm>>>(xh, xl, wqh, wql, cosb, sinb, nullptr, N1, CH);
    }

    // 2) flash attention (HMMA, pipelined) -> split ctx
    {
        dim3 g2(SEQ / 128, Bq * NH);
        flash_hmma<<<g2, 256, shm_flash>>>();
    }

    // 3) out = ctx @ Wproj^T + bproj (8192 x 768, K=768)
    {
        __nv_bfloat16 *ch, *cl, *wph, *wpl;
        cudaGetSymbolAddress((void**)&ch,  g_ch);
        cudaGetSymbolAddress((void**)&cl,  g_cl);
        cudaGetSymbolAddress((void**)&wph, g_wph);
        cudaGetSymbolAddress((void**)&wpl, g_wpl);
        dim3 g3(CH / 128, MTOT / 128);
        gemm_bf16<1><<<g3, 256, shm_gemm>>>(ch, cl, wph, wpl, bproj, nullptr, out, CH, CH);
    }
}